// round 2
// baseline (speedup 1.0000x reference)
#include <cuda_runtime.h>
#include <cstdint>

#define B_ 128
#define L_ 1024
#define H_ 256
#define E_ 128
#define V_ 50000
#define X_ 100
#define VX_ 50100
#define NTILE 391

// d_out float offsets (tuple order: final_dist, h, c, c_t, a, p_gen, coverage_next)
#define O_FD  0
#define O_H   6412800
#define O_C   6445568
#define O_CT  6478336
#define O_A   6543872
#define O_PG  6674944
#define O_COV 6675072

// ---------------- static device scratch (no allocations) ----------------
__device__ __align__(256) float g_x[B_ * E_];                 // [b][e]
__device__ __align__(256) float g_gates[4 * H_ * B_];         // [j][b]
__device__ __align__(256) float g_dec[B_ * 2 * H_];           // [b][d]
__device__ __align__(256) float g_energy[B_ * L_];            // [b][l]
__device__ __align__(256) float g_ctp[B_ * 16 * 2 * H_];      // [b][chunk][d]
__device__ __align__(256) float g_hid[B_ * H_];               // [b][j]
__device__ __align__(256) float g_logits[B_ * V_];            // [b][v]
__device__ __align__(256) float g_tmax[B_ * NTILE];
__device__ __align__(256) float g_tsum[B_ * NTILE];
__device__ __align__(256) float g_M[B_];
__device__ __align__(256) float g_scale[B_];

// ---------------- helpers ----------------
__device__ __forceinline__ float fsig(float x) {
    return __fdividef(1.0f, 1.0f + __expf(-x));
}
__device__ __forceinline__ float ftanh(float x) {
    float e = __expf(2.0f * x);
    return 1.0f - __fdividef(2.0f, 1.0f + e);
}
__device__ __forceinline__ void fma2(unsigned long long& d, unsigned long long a, unsigned long long b) {
    asm("fma.rn.f32x2 %0, %1, %2, %0;" : "+l"(d) : "l"(a), "l"(b));
}
__device__ __forceinline__ unsigned long long pk2(float lo, float hi) {
    unsigned long long r; asm("mov.b64 %0, {%1, %2};" : "=l"(r) : "f"(lo), "f"(hi)); return r;
}
__device__ __forceinline__ float2 upk2(unsigned long long v) {
    float2 r; asm("mov.b64 {%0, %1}, %2;" : "=f"(r.x), "=f"(r.y) : "l"(v)); return r;
}

// =============== K1: x = [c_t_1, emb(y_t)] @ xctx_W.T + xctx_b ===============
__global__ void k_x(const int* __restrict__ y_t, const float* __restrict__ c_t_1,
                    const float* __restrict__ embed_W,
                    const float* __restrict__ xctx_W, const float* __restrict__ xctx_b) {
    int b = blockIdx.x, t = threadIdx.x;          // 128 threads
    __shared__ float sin_[640];
    for (int i = t; i < 512; i += 128) sin_[i] = c_t_1[b * 512 + i];
    int y = y_t[b];
    sin_[512 + t] = embed_W[y * 128 + t];
    __syncthreads();
    float acc = xctx_b[t];
    const float4* W4 = (const float4*)(xctx_W + t * 640);
    const float4* S4 = (const float4*)sin_;
#pragma unroll 8
    for (int k = 0; k < 160; k++) {
        float4 w = W4[k], s = S4[k];
        acc += w.x * s.x + w.y * s.y + w.z * s.z + w.w * s.w;
    }
    g_x[b * 128 + t] = acc;
}

// =============== K2: gates GEMM -> g_gates[j][b] ===============
__global__ void k_gates(const float* __restrict__ h0,
                        const float* __restrict__ Wih, const float* __restrict__ Whh,
                        const float* __restrict__ bih, const float* __restrict__ bhh) {
    int j0 = blockIdx.x * 128, b0 = blockIdx.y * 8;
    __shared__ float sx[8][128];
    __shared__ float sh[8][256];
    int tid = threadIdx.x;                         // 256 threads
    for (int i = tid; i < 1024; i += 256) sx[i >> 7][i & 127] = g_x[(b0 + (i >> 7)) * 128 + (i & 127)];
    for (int i = tid; i < 2048; i += 256) sh[i >> 8][i & 255] = h0[(b0 + (i >> 8)) * 256 + (i & 255)];
    __syncthreads();
    int j = j0 + (tid & 127);
    int bq = tid >> 7;                             // 0/1 -> handles 4 b rows
    float acc[4];
    float bias = bih[j] + bhh[j];
#pragma unroll
    for (int bb = 0; bb < 4; bb++) acc[bb] = bias;
    const float4* Wi4 = (const float4*)Wih;
    const float4* Wh4 = (const float4*)Whh;
#pragma unroll 4
    for (int k = 0; k < 32; k++) {
        float4 w = Wi4[j * 32 + k];
#pragma unroll
        for (int bb = 0; bb < 4; bb++) {
            float4 s = ((const float4*)sx[bq * 4 + bb])[k];
            acc[bb] += w.x * s.x + w.y * s.y + w.z * s.z + w.w * s.w;
        }
    }
#pragma unroll 4
    for (int k = 0; k < 64; k++) {
        float4 w = Wh4[j * 64 + k];
#pragma unroll
        for (int bb = 0; bb < 4; bb++) {
            float4 s = ((const float4*)sh[bq * 4 + bb])[k];
            acc[bb] += w.x * s.x + w.y * s.y + w.z * s.z + w.w * s.w;
        }
    }
#pragma unroll
    for (int bb = 0; bb < 4; bb++)
        g_gates[j * 128 + b0 + bq * 4 + bb] = acc[bb];
}

// =============== K3: LSTM pointwise ===============
__global__ void k_lstm(const float* __restrict__ c0, float* __restrict__ outp) {
    int i = blockIdx.x * 256 + threadIdx.x;        // 32768
    int t = i >> 7, b = i & 127;
    float gi = g_gates[i];
    float gf = g_gates[i + 32768];
    float gg = g_gates[i + 65536];
    float go = g_gates[i + 98304];
    float c0v = c0[b * 256 + t];
    float cc = fsig(gf) * c0v + fsig(gi) * ftanh(gg);
    float hh = fsig(go) * ftanh(cc);
    outp[O_H + b * 256 + t] = hh;
    outp[O_C + b * 256 + t] = cc;
}

// =============== K4: dec_feats = s_t_hat @ Ws_W.T + Ws_b ===============
__global__ void k_dec(const float* __restrict__ outp,
                      const float* __restrict__ Ws_W, const float* __restrict__ Ws_b) {
    int d0 = blockIdx.x * 128, b0 = blockIdx.y * 8;
    __shared__ float ss[8][512];
    int tid = threadIdx.x;                          // 256
    for (int i = tid; i < 4096; i += 256) {
        int bi = i >> 9, k = i & 511;
        ss[bi][k] = (k < 256) ? outp[O_H + (b0 + bi) * 256 + k]
                              : outp[O_C + (b0 + bi) * 256 + (k - 256)];
    }
    __syncthreads();
    int d = d0 + (tid & 127);
    int bq = tid >> 7;
    float acc[4];
    float bias = Ws_b[d];
#pragma unroll
    for (int bb = 0; bb < 4; bb++) acc[bb] = bias;
    const float4* W4 = (const float4*)Ws_W;
#pragma unroll 4
    for (int k = 0; k < 128; k++) {
        float4 w = W4[d * 128 + k];
#pragma unroll
        for (int bb = 0; bb < 4; bb++) {
            float4 s = ((const float4*)ss[bq * 4 + bb])[k];
            acc[bb] += w.x * s.x + w.y * s.y + w.z * s.z + w.w * s.w;
        }
    }
#pragma unroll
    for (int bb = 0; bb < 4; bb++)
        g_dec[(b0 + bq * 4 + bb) * 512 + d] = acc[bb];
}

// =============== K5: attention energy (streams enc_feats) ===============
__global__ void k_energy(const float* __restrict__ enc_feats,
                         const float* __restrict__ coverage,
                         const float* __restrict__ Wc_W, const float* __restrict__ v_W) {
    int idx0 = blockIdx.x * 8;
    int b = idx0 >> 10;                             // same for all 8 warps
    __shared__ float sdec[512], swc[512], sv[512];
    int tid = threadIdx.x;                          // 256
    for (int i = tid; i < 512; i += 256) {
        sdec[i] = g_dec[b * 512 + i];
        swc[i]  = Wc_W[i];
        sv[i]   = v_W[i];
    }
    __syncthreads();
    int w = tid >> 5, lane = tid & 31;
    int idx = idx0 + w;
    float cov = coverage[idx];
    const float* base = enc_feats + (size_t)idx * 512;
    float e = 0.0f;
#pragma unroll
    for (int c = 0; c < 4; c++) {
        int d0 = c * 128 + lane * 4;
        float4 f  = *(const float4*)(base + d0);
        float4 dv = *(const float4*)(sdec + d0);
        float4 wv = *(const float4*)(swc + d0);
        float4 vv = *(const float4*)(sv + d0);
        e += ftanh(f.x + dv.x + cov * wv.x) * vv.x;
        e += ftanh(f.y + dv.y + cov * wv.y) * vv.y;
        e += ftanh(f.z + dv.z + cov * wv.z) * vv.z;
        e += ftanh(f.w + dv.w + cov * wv.w) * vv.w;
    }
#pragma unroll
    for (int o = 16; o; o >>= 1) e += __shfl_xor_sync(0xffffffffu, e, o);
    if (lane == 0) g_energy[idx] = e;
}

// =============== K6: softmax over L, mask, renorm, coverage_next ===============
__global__ void k_softmax_a(const float* __restrict__ mask, const float* __restrict__ coverage,
                            float* __restrict__ outp) {
    int b = blockIdx.x, tid = threadIdx.x;          // 256
    __shared__ float red[256];
    float e[4];
#pragma unroll
    for (int j = 0; j < 4; j++) e[j] = g_energy[b * 1024 + tid + j * 256];
    float m = fmaxf(fmaxf(e[0], e[1]), fmaxf(e[2], e[3]));
    red[tid] = m; __syncthreads();
    for (int s = 128; s > 0; s >>= 1) { if (tid < s) red[tid] = fmaxf(red[tid], red[tid + s]); __syncthreads(); }
    float M = red[0]; __syncthreads();
    float ev[4], sum = 0.0f;
#pragma unroll
    for (int j = 0; j < 4; j++) {
        ev[j] = __expf(e[j] - M) * mask[b * 1024 + tid + j * 256];
        sum += ev[j];
    }
    red[tid] = sum; __syncthreads();
    for (int s = 128; s > 0; s >>= 1) { if (tid < s) red[tid] += red[tid + s]; __syncthreads(); }
    float inv = __fdividef(1.0f, red[0]);
#pragma unroll
    for (int j = 0; j < 4; j++) {
        int i = b * 1024 + tid + j * 256;
        float a = ev[j] * inv;
        outp[O_A + i] = a;
        outp[O_COV + i] = coverage[i] + a;
    }
}

// =============== K7: c_t partials (streams enc_outs) ===============
__global__ void k_ctx(const float* __restrict__ enc_outs, const float* __restrict__ outp) {
    int chunk = blockIdx.x, b = blockIdx.y;
    __shared__ float sa[64];
    int tid = threadIdx.x;                          // 256
    if (tid < 64) sa[tid] = outp[O_A + b * 1024 + chunk * 64 + tid];
    __syncthreads();
    const float2* p = (const float2*)(enc_outs + ((size_t)b * 1024 + chunk * 64) * 512);
    float2 acc = make_float2(0.0f, 0.0f);
#pragma unroll 8
    for (int i = 0; i < 64; i++) {
        float2 v = p[i * 256 + tid];
        float a = sa[i];
        acc.x += a * v.x;
        acc.y += a * v.y;
    }
    *(float2*)&g_ctp[(b * 16 + chunk) * 512 + 2 * tid] = acc;
}

// =============== K8: reduce c_t, p_gen ===============
__global__ void k_finalize(const float* __restrict__ pgen_W, const float* __restrict__ pgen_b,
                           float* __restrict__ outp) {
    int b = blockIdx.x, tid = threadIdx.x;          // 512
    __shared__ float sct[512];
    __shared__ float red[512];
    float s = 0.0f;
#pragma unroll
    for (int ch = 0; ch < 16; ch++) s += g_ctp[(b * 16 + ch) * 512 + tid];
    sct[tid] = s;
    outp[O_CT + b * 512 + tid] = s;
    __syncthreads();
    // pgen dot over [c_t(512), h(256), c(256), x(128)]
    float p = pgen_W[tid] * sct[tid];
    float z2 = (tid < 256) ? outp[O_H + b * 256 + tid] : outp[O_C + b * 256 + (tid - 256)];
    p += pgen_W[512 + tid] * z2;
    if (tid < 128) p += pgen_W[1024 + tid] * g_x[b * 128 + tid];
    red[tid] = p; __syncthreads();
    for (int st = 256; st > 0; st >>= 1) { if (tid < st) red[tid] += red[tid + st]; __syncthreads(); }
    if (tid == 0) outp[O_PG + b] = fsig(red[0] + pgen_b[0]);
}

// =============== K9: out_hid = [h, c_t] @ proj_W.T + proj_b ===============
__global__ void k_hid(const float* __restrict__ outp,
                      const float* __restrict__ proj_W, const float* __restrict__ proj_b) {
    int j0 = blockIdx.x * 128, b0 = blockIdx.y * 8;
    __shared__ float scat[8][768];
    int tid = threadIdx.x;                          // 256
    for (int i = tid; i < 6144; i += 256) {
        int bi = i / 768, k = i % 768;
        scat[bi][k] = (k < 256) ? outp[O_H + (b0 + bi) * 256 + k]
                                : outp[O_CT + (b0 + bi) * 512 + (k - 256)];
    }
    __syncthreads();
    int j = j0 + (tid & 127);
    int bq = tid >> 7;
    float acc[4];
    float bias = proj_b[j];
#pragma unroll
    for (int bb = 0; bb < 4; bb++) acc[bb] = bias;
    const float4* W4 = (const float4*)proj_W;
#pragma unroll 4
    for (int k = 0; k < 192; k++) {
        float4 w = W4[j * 192 + k];
#pragma unroll
        for (int bb = 0; bb < 4; bb++) {
            float4 s = ((const float4*)scat[bq * 4 + bb])[k];
            acc[bb] += w.x * s.x + w.y * s.y + w.z * s.z + w.w * s.w;
        }
    }
#pragma unroll
    for (int bb = 0; bb < 4; bb++)
        g_hid[(b0 + bq * 4 + bb) * 256 + j] = acc[bb];
}

// =============== K10: logits GEMM (f32x2) + per-tile softmax partials ===============
__global__ void __launch_bounds__(256, 2)
k_logits(const float* __restrict__ outW, const float* __restrict__ outb) {
    int v0 = blockIdx.x * 128;
    __shared__ float sA[16][128];
    __shared__ float sB[16][128];
    __shared__ float red[128][17];
    __shared__ float srm[128];
    int tid = threadIdx.x;
    int tx = tid & 15, ty = tid >> 4;
    unsigned long long acc[4][8];
#pragma unroll
    for (int p = 0; p < 4; p++)
#pragma unroll
        for (int j = 0; j < 8; j++) acc[p][j] = 0ull;

    for (int k0 = 0; k0 < 256; k0 += 16) {
        for (int i = tid; i < 2048; i += 256) {
            int kk = i & 15, bb = i >> 4;
            sA[kk][bb] = g_hid[bb * 256 + k0 + kk];
        }
        for (int i = tid; i < 2048; i += 256) {
            int kk = i & 15, j = i >> 4;
            int v = v0 + j;
            sB[kk][j] = (v < V_) ? outW[v * 256 + k0 + kk] : 0.0f;
        }
        __syncthreads();
#pragma unroll
        for (int kk = 0; kk < 16; kk++) {
            float4 a0 = *(const float4*)&sA[kk][ty * 8];
            float4 a1 = *(const float4*)&sA[kk][ty * 8 + 4];
            float4 w0 = *(const float4*)&sB[kk][tx * 8];
            float4 w1 = *(const float4*)&sB[kk][tx * 8 + 4];
            unsigned long long pa[4];
            pa[0] = pk2(a0.x, a0.y); pa[1] = pk2(a0.z, a0.w);
            pa[2] = pk2(a1.x, a1.y); pa[3] = pk2(a1.z, a1.w);
            float wv[8] = {w0.x, w0.y, w0.z, w0.w, w1.x, w1.y, w1.z, w1.w};
#pragma unroll
            for (int j = 0; j < 8; j++) {
                unsigned long long wp = pk2(wv[j], wv[j]);
#pragma unroll
                for (int p = 0; p < 4; p++) fma2(acc[p][j], pa[p], wp);
            }
        }
        __syncthreads();
    }

    // epilogue: bias, store logits, per-tile max & sumexp per row
    float lg[8][8];
    float bias[8];
    bool valid[8];
#pragma unroll
    for (int j = 0; j < 8; j++) {
        int v = v0 + tx * 8 + j;
        valid[j] = v < V_;
        bias[j] = valid[j] ? outb[v] : 0.0f;
    }
#pragma unroll
    for (int p = 0; p < 4; p++)
#pragma unroll
        for (int j = 0; j < 8; j++) {
            float2 f = upk2(acc[p][j]);
            lg[2 * p][j]     = f.x + bias[j];
            lg[2 * p + 1][j] = f.y + bias[j];
        }
#pragma unroll
    for (int bb = 0; bb < 8; bb++) {
        int rb = ty * 8 + bb;
        float mx = -1e30f;
#pragma unroll
        for (int j = 0; j < 8; j++) {
            if (valid[j]) {
                g_logits[rb * V_ + v0 + tx * 8 + j] = lg[bb][j];
                mx = fmaxf(mx, lg[bb][j]);
            }
        }
        red[rb][tx] = mx;
    }
    __syncthreads();
    if (tid < 128) {
        float mx = red[tid][0];
#pragma unroll
        for (int i = 1; i < 16; i++) mx = fmaxf(mx, red[tid][i]);
        srm[tid] = mx;
    }
    __syncthreads();
#pragma unroll
    for (int bb = 0; bb < 8; bb++) {
        int rb = ty * 8 + bb;
        float rm = srm[rb], s = 0.0f;
#pragma unroll
        for (int j = 0; j < 8; j++)
            if (valid[j]) s += __expf(lg[bb][j] - rm);
        red[rb][tx] = s;
    }
    __syncthreads();
    if (tid < 128) {
        float s = 0.0f;
#pragma unroll
        for (int i = 0; i < 16; i++) s += red[tid][i];
        g_tmax[tid * NTILE + blockIdx.x] = srm[tid];
        g_tsum[tid * NTILE + blockIdx.x] = s;
    }
}

// =============== K11: combine tile partials -> M, scale = p_gen / S ===============
__global__ void k_combine(const float* __restrict__ outp) {
    int b = blockIdx.x, tid = threadIdx.x;          // 128
    __shared__ float red[128];
    float m = -1e30f;
    for (int i = tid; i < NTILE; i += 128) m = fmaxf(m, g_tmax[b * NTILE + i]);
    red[tid] = m; __syncthreads();
    for (int s = 64; s > 0; s >>= 1) { if (tid < s) red[tid] = fmaxf(red[tid], red[tid + s]); __syncthreads(); }
    float M = red[0]; __syncthreads();
    float sum = 0.0f;
    for (int i = tid; i < NTILE; i += 128)
        sum += g_tsum[b * NTILE + i] * __expf(g_tmax[b * NTILE + i] - M);
    red[tid] = sum; __syncthreads();
    for (int s = 64; s > 0; s >>= 1) { if (tid < s) red[tid] += red[tid + s]; __syncthreads(); }
    if (tid == 0) {
        g_M[b] = M;
        g_scale[b] = __fdividef(outp[O_PG + b], red[0]);
    }
}

// =============== K12: final vocab dist (+extra zeros) ===============
__global__ void k_final_vocab(const float* __restrict__ extra_zeros, float* __restrict__ outp) {
    int v = blockIdx.x * 256 + threadIdx.x;
    int b = blockIdx.y;
    if (v < V_) {
        outp[O_FD + b * VX_ + v] = g_scale[b] * __expf(g_logits[b * V_ + v] - g_M[b]);
    } else if (v < VX_) {
        outp[O_FD + b * VX_ + v] = extra_zeros[b * X_ + (v - V_)];
    }
}

// =============== K13: pointer scatter-add ===============
__global__ void k_scatter(const int* __restrict__ ext_vocab, float* __restrict__ outp) {
    int i = blockIdx.x * 256 + threadIdx.x;         // B*L
    int b = i >> 10;
    float pg = outp[O_PG + b];
    float av = outp[O_A + i];
    atomicAdd(&outp[O_FD + b * VX_ + ext_vocab[i]], (1.0f - pg) * av);
}

// ======================================================================
extern "C" void kernel_launch(void* const* d_in, const int* in_sizes, int n_in,
                              void* d_out, int out_size) {
    (void)in_sizes; (void)n_in; (void)out_size;
    const int*   y_t       = (const int*)d_in[0];
    const float* h0        = (const float*)d_in[1];
    const float* c0        = (const float*)d_in[2];
    const float* enc_outs  = (const float*)d_in[3];
    const float* enc_feats = (const float*)d_in[4];
    const float* mask      = (const float*)d_in[5];
    const float* c_t_1     = (const float*)d_in[6];
    const float* extra_z   = (const float*)d_in[7];
    const int*   ext_vocab = (const int*)d_in[8];
    const float* coverage  = (const float*)d_in[9];
    const float* embed_W   = (const float*)d_in[10];
    const float* Wih       = (const float*)d_in[11];
    const float* Whh       = (const float*)d_in[12];
    const float* bih       = (const float*)d_in[13];
    const float* bhh       = (const float*)d_in[14];
    const float* xctx_W    = (const float*)d_in[15];
    const float* xctx_b    = (const float*)d_in[16];
    const float* Ws_W      = (const float*)d_in[17];
    const float* Ws_b      = (const float*)d_in[18];
    const float* Wc_W      = (const float*)d_in[19];
    const float* v_W       = (const float*)d_in[20];
    const float* pgen_W    = (const float*)d_in[21];
    const float* pgen_b    = (const float*)d_in[22];
    const float* proj_W    = (const float*)d_in[23];
    const float* proj_b    = (const float*)d_in[24];
    const float* out_W     = (const float*)d_in[25];
    const float* out_b     = (const float*)d_in[26];
    float* outp = (float*)d_out;

    k_x<<<B_, 128>>>(y_t, c_t_1, embed_W, xctx_W, xctx_b);
    k_gates<<<dim3(8, 16), 256>>>(h0, Wih, Whh, bih, bhh);
    k_lstm<<<128, 256>>>(c0, outp);
    k_dec<<<dim3(4, 16), 256>>>(outp, Ws_W, Ws_b);
    k_energy<<<B_ * L_ / 8, 256>>>(enc_feats, coverage, Wc_W, v_W);
    k_softmax_a<<<B_, 256>>>(mask, coverage, outp);
    k_ctx<<<dim3(16, B_), 256>>>(enc_outs, outp);
    k_finalize<<<B_, 512>>>(pgen_W, pgen_b, outp);
    k_hid<<<dim3(2, 16), 256>>>(outp, proj_W, proj_b);
    k_logits<<<NTILE, 256>>>(out_W, out_b);
    k_combine<<<B_, 128>>>(outp);
    k_final_vocab<<<dim3(196, B_), 256>>>(extra_z, outp);
    k_scatter<<<B_ * L_ / 256, 256>>>(ext_vocab, outp);
}

// round 3
// speedup vs baseline: 1.2309x; 1.2309x over previous
#include <cuda_runtime.h>
#include <cstdint>

#define B_ 128
#define L_ 1024
#define H_ 256
#define E_ 128
#define V_ 50000
#define X_ 100
#define VX_ 50100
#define NTILE 391

// d_out float offsets (tuple order: final_dist, h, c, c_t, a, p_gen, coverage_next)
#define O_FD  0
#define O_H   6412800
#define O_C   6445568
#define O_CT  6478336
#define O_A   6543872
#define O_PG  6674944
#define O_COV 6675072

// ---------------- static device scratch (no allocations) ----------------
// all activation/result matrices are column-major: [k][128 b]
__device__ __align__(256) float g_prepT[640 * B_];      // [c_t_1(512); emb(128)]
__device__ __align__(256) float g_h0T[256 * B_];
__device__ __align__(256) float g_xT[E_ * B_];          // 16384
__device__ __align__(256) float g_gatesT[4 * H_ * B_];  // 131072
__device__ __align__(256) float g_hcT[2 * H_ * B_];     // [h(256); c(256)]
__device__ __align__(256) float g_decT[2 * H_ * B_];    // 65536
__device__ __align__(256) float g_ctT[2 * H_ * B_];     // c_t transposed
__device__ __align__(256) float g_hidT[H_ * B_];        // 32768
__device__ __align__(256) float g_energy[B_ * L_];
__device__ __align__(256) float g_ctp[B_ * 16 * 2 * H_];
__device__ __align__(256) float g_logits[B_ * V_];
__device__ __align__(256) float g_tmax[B_ * NTILE];
__device__ __align__(256) float g_tsum[B_ * NTILE];
__device__ __align__(256) float g_M[B_];
__device__ __align__(256) float g_scale[B_];

// ---------------- helpers ----------------
__device__ __forceinline__ float fsig(float x) {
    return __fdividef(1.0f, 1.0f + __expf(-x));
}
__device__ __forceinline__ float ftanh(float x) {
    float e = __expf(2.0f * x);
    return 1.0f - __fdividef(2.0f, 1.0f + e);
}
__device__ __forceinline__ void fma2(unsigned long long& d, unsigned long long a, unsigned long long b) {
    asm("fma.rn.f32x2 %0, %1, %2, %0;" : "+l"(d) : "l"(a), "l"(b));
}
__device__ __forceinline__ unsigned long long pk2(float lo, float hi) {
    unsigned long long r; asm("mov.b64 %0, {%1, %2};" : "=l"(r) : "f"(lo), "f"(hi)); return r;
}
__device__ __forceinline__ float2 upk2(unsigned long long v) {
    float2 r; asm("mov.b64 {%0, %1}, %2;" : "=f"(r.x), "=f"(r.y) : "l"(v)); return r;
}

// =============== K0: zero GEMM accumulators ===============
__global__ void k_zero() {
    int i = blockIdx.x * 256 + threadIdx.x;       // grid 512 -> i < 131072
    if (i < E_ * B_)      g_xT[i] = 0.0f;
    if (i < 4 * H_ * B_)  g_gatesT[i] = 0.0f;
    if (i < 2 * H_ * B_)  g_decT[i] = 0.0f;
    if (i < H_ * B_)      g_hidT[i] = 0.0f;
}

// =============== K0b: prep transposed activations ===============
__global__ void k_prep(const int* __restrict__ y_t, const float* __restrict__ c_t_1,
                       const float* __restrict__ embed_W, const float* __restrict__ h0) {
    int b = blockIdx.x, t = threadIdx.x;          // 128 blocks x 256
    for (int k = t; k < 512; k += 256) g_prepT[k * 128 + b] = c_t_1[b * 512 + k];
    int y = y_t[b];
    if (t < 128) g_prepT[(512 + t) * 128 + b] = embed_W[y * 128 + t];
    if (t < 256) g_h0T[t * 128 + b] = h0[b * 256 + t];
}

// =============== unified small GEMM ===============
// outT[j][b] (+)= sum_k act[k][b] * W[j][k] (+bias on z==0)
// act split into two col-major segments; W segments have independent base/row-stride.
// grid: (J/32, 4, KSPLIT); block 256 = 8 warps (4 j each) x 32 b-lanes.
__global__ void __launch_bounds__(256) k_gemm(
    const float* __restrict__ actA, const float* __restrict__ WA, int sWA, int KA,
    const float* __restrict__ actB, const float* __restrict__ WB, int sWB,
    const float* __restrict__ bias1, const float* __restrict__ bias2,
    float* __restrict__ outT, int CPS)
{
    __shared__ float s_act[32][65];
    __shared__ float s_w[32][64];
    int tid = threadIdx.x;
    int lane = tid & 31, wp = tid >> 5;
    int j0 = blockIdx.x * 32;
    int b  = blockIdx.y * 32 + lane;
    int c0 = blockIdx.z * CPS;
    float acc0 = 0.0f, acc1 = 0.0f, acc2 = 0.0f, acc3 = 0.0f;

    for (int c = 0; c < CPS; c++) {
        int k0 = (c0 + c) * 64;
        const float* asrc; const float* wsrc; int ws; int kr;
        if (k0 < KA) { asrc = actA; wsrc = WA; ws = sWA; kr = k0; }
        else         { asrc = actB; wsrc = WB; ws = sWB; kr = k0 - KA; }
        // stage activations: warp wp loads k = wp + 8r, lanes over b (coalesced)
#pragma unroll
        for (int r = 0; r < 8; r++) {
            int k = r * 8 + wp;
            s_act[lane][k] = asrc[(kr + k) * 128 + b];
        }
        // stage W: 512 float4, 2 per thread (coalesced along k)
        {
            int idx = tid * 2;
            int j = idx >> 4, f = (idx & 15) * 4;
            float4 v = *(const float4*)&wsrc[(j0 + j) * ws + kr + f];
            *(float4*)&s_w[j][f] = v;
            idx++;
            j = idx >> 4; f = (idx & 15) * 4;
            v = *(const float4*)&wsrc[(j0 + j) * ws + kr + f];
            *(float4*)&s_w[j][f] = v;
        }
        __syncthreads();
#pragma unroll
        for (int kk = 0; kk < 64; kk += 4) {
            float a0 = s_act[lane][kk + 0];
            float a1 = s_act[lane][kk + 1];
            float a2 = s_act[lane][kk + 2];
            float a3 = s_act[lane][kk + 3];
            float4 w0 = *(const float4*)&s_w[wp * 4 + 0][kk];
            float4 w1 = *(const float4*)&s_w[wp * 4 + 1][kk];
            float4 w2 = *(const float4*)&s_w[wp * 4 + 2][kk];
            float4 w3 = *(const float4*)&s_w[wp * 4 + 3][kk];
            acc0 += w0.x * a0 + w0.y * a1 + w0.z * a2 + w0.w * a3;
            acc1 += w1.x * a0 + w1.y * a1 + w1.z * a2 + w1.w * a3;
            acc2 += w2.x * a0 + w2.y * a1 + w2.z * a2 + w2.w * a3;
            acc3 += w3.x * a0 + w3.y * a1 + w3.z * a2 + w3.w * a3;
        }
        __syncthreads();
    }
    int j = j0 + wp * 4;
    if (blockIdx.z == 0 && bias1) {
        acc0 += bias1[j + 0]; acc1 += bias1[j + 1]; acc2 += bias1[j + 2]; acc3 += bias1[j + 3];
        if (bias2) {
            acc0 += bias2[j + 0]; acc1 += bias2[j + 1]; acc2 += bias2[j + 2]; acc3 += bias2[j + 3];
        }
    }
    atomicAdd(&outT[(j + 0) * 128 + b], acc0);
    atomicAdd(&outT[(j + 1) * 128 + b], acc1);
    atomicAdd(&outT[(j + 2) * 128 + b], acc2);
    atomicAdd(&outT[(j + 3) * 128 + b], acc3);
}

// =============== K3: LSTM pointwise ===============
__global__ void k_lstm(const float* __restrict__ c0, float* __restrict__ outp) {
    int i = blockIdx.x * 256 + threadIdx.x;        // 32768
    int t = i >> 7, b = i & 127;
    float gi = g_gatesT[i];
    float gf = g_gatesT[i + 32768];
    float gg = g_gatesT[i + 65536];
    float go = g_gatesT[i + 98304];
    float c0v = c0[b * 256 + t];
    float cc = fsig(gf) * c0v + fsig(gi) * ftanh(gg);
    float hh = fsig(go) * ftanh(cc);
    outp[O_H + b * 256 + t] = hh;
    outp[O_C + b * 256 + t] = cc;
    g_hcT[t * 128 + b] = hh;
    g_hcT[(256 + t) * 128 + b] = cc;
}

// =============== K5: attention energy (streams enc_feats) ===============
__global__ void k_energy(const float* __restrict__ enc_feats,
                         const float* __restrict__ coverage,
                         const float* __restrict__ Wc_W, const float* __restrict__ v_W) {
    int idx0 = blockIdx.x * 8;
    int b = idx0 >> 10;
    __shared__ float sdec[512], swc[512], sv[512];
    int tid = threadIdx.x;                          // 256
    for (int i = tid; i < 512; i += 256) {
        sdec[i] = g_decT[i * 128 + b];
        swc[i]  = Wc_W[i];
        sv[i]   = v_W[i];
    }
    __syncthreads();
    int w = tid >> 5, lane = tid & 31;
    int idx = idx0 + w;
    float cov = coverage[idx];
    const float* base = enc_feats + (size_t)idx * 512;
    float e = 0.0f;
#pragma unroll
    for (int c = 0; c < 4; c++) {
        int d0 = c * 128 + lane * 4;
        float4 f  = *(const float4*)(base + d0);
        float4 dv = *(const float4*)(sdec + d0);
        float4 wv = *(const float4*)(swc + d0);
        float4 vv = *(const float4*)(sv + d0);
        e += ftanh(f.x + dv.x + cov * wv.x) * vv.x;
        e += ftanh(f.y + dv.y + cov * wv.y) * vv.y;
        e += ftanh(f.z + dv.z + cov * wv.z) * vv.z;
        e += ftanh(f.w + dv.w + cov * wv.w) * vv.w;
    }
#pragma unroll
    for (int o = 16; o; o >>= 1) e += __shfl_xor_sync(0xffffffffu, e, o);
    if (lane == 0) g_energy[idx] = e;
}

// =============== K6: softmax over L, mask, renorm, coverage_next ===============
__global__ void k_softmax_a(const float* __restrict__ mask, const float* __restrict__ coverage,
                            float* __restrict__ outp) {
    int b = blockIdx.x, tid = threadIdx.x;          // 256
    __shared__ float red[256];
    float e[4];
#pragma unroll
    for (int j = 0; j < 4; j++) e[j] = g_energy[b * 1024 + tid + j * 256];
    float m = fmaxf(fmaxf(e[0], e[1]), fmaxf(e[2], e[3]));
    red[tid] = m; __syncthreads();
    for (int s = 128; s > 0; s >>= 1) { if (tid < s) red[tid] = fmaxf(red[tid], red[tid + s]); __syncthreads(); }
    float M = red[0]; __syncthreads();
    float ev[4], sum = 0.0f;
#pragma unroll
    for (int j = 0; j < 4; j++) {
        ev[j] = __expf(e[j] - M) * mask[b * 1024 + tid + j * 256];
        sum += ev[j];
    }
    red[tid] = sum; __syncthreads();
    for (int s = 128; s > 0; s >>= 1) { if (tid < s) red[tid] += red[tid + s]; __syncthreads(); }
    float inv = __fdividef(1.0f, red[0]);
#pragma unroll
    for (int j = 0; j < 4; j++) {
        int i = b * 1024 + tid + j * 256;
        float a = ev[j] * inv;
        outp[O_A + i] = a;
        outp[O_COV + i] = coverage[i] + a;
    }
}

// =============== K7: c_t partials (streams enc_outs) ===============
__global__ void k_ctx(const float* __restrict__ enc_outs, const float* __restrict__ outp) {
    int chunk = blockIdx.x, b = blockIdx.y;
    __shared__ float sa[64];
    int tid = threadIdx.x;                          // 256
    if (tid < 64) sa[tid] = outp[O_A + b * 1024 + chunk * 64 + tid];
    __syncthreads();
    const float2* p = (const float2*)(enc_outs + ((size_t)b * 1024 + chunk * 64) * 512);
    float2 acc = make_float2(0.0f, 0.0f);
#pragma unroll 8
    for (int i = 0; i < 64; i++) {
        float2 v = p[i * 256 + tid];
        float a = sa[i];
        acc.x += a * v.x;
        acc.y += a * v.y;
    }
    *(float2*)&g_ctp[(b * 16 + chunk) * 512 + 2 * tid] = acc;
}

// =============== K8: reduce c_t, p_gen ===============
__global__ void k_finalize(const float* __restrict__ pgen_W, const float* __restrict__ pgen_b,
                           float* __restrict__ outp) {
    int b = blockIdx.x, tid = threadIdx.x;          // 512
    __shared__ float sct[512];
    __shared__ float red[512];
    float s = 0.0f;
#pragma unroll
    for (int ch = 0; ch < 16; ch++) s += g_ctp[(b * 16 + ch) * 512 + tid];
    sct[tid] = s;
    outp[O_CT + b * 512 + tid] = s;
    g_ctT[tid * 128 + b] = s;
    __syncthreads();
    // pgen dot over [c_t(512), h(256), c(256), x(128)]
    float p = pgen_W[tid] * sct[tid];
    float z2 = (tid < 256) ? outp[O_H + b * 256 + tid] : outp[O_C + b * 256 + (tid - 256)];
    p += pgen_W[512 + tid] * z2;
    if (tid < 128) p += pgen_W[1024 + tid] * g_xT[tid * 128 + b];
    red[tid] = p; __syncthreads();
    for (int st = 256; st > 0; st >>= 1) { if (tid < st) red[tid] += red[tid + st]; __syncthreads(); }
    if (tid == 0) outp[O_PG + b] = fsig(red[0] + pgen_b[0]);
}

// =============== K10: logits GEMM (f32x2) + per-tile softmax partials ===============
__global__ void __launch_bounds__(256, 2)
k_logits(const float* __restrict__ outW, const float* __restrict__ outb) {
    int v0 = blockIdx.x * 128;
    __shared__ float sA[16][128];
    __shared__ float sB[16][128];
    __shared__ float red[128][17];
    __shared__ float srm[128];
    int tid = threadIdx.x;
    int tx = tid & 15, ty = tid >> 4;
    unsigned long long acc[4][8];
#pragma unroll
    for (int p = 0; p < 4; p++)
#pragma unroll
        for (int j = 0; j < 8; j++) acc[p][j] = 0ull;

    for (int k0 = 0; k0 < 256; k0 += 16) {
        for (int i = tid; i < 2048; i += 256) {
            int bb = i & 127, kk = i >> 7;
            sA[kk][bb] = g_hidT[(k0 + kk) * 128 + bb];
        }
        for (int i = tid; i < 2048; i += 256) {
            int kk = i & 15, j = i >> 4;
            int v = v0 + j;
            sB[kk][j] = (v < V_) ? outW[v * 256 + k0 + kk] : 0.0f;
        }
        __syncthreads();
#pragma unroll
        for (int kk = 0; kk < 16; kk++) {
            float4 a0 = *(const float4*)&sA[kk][ty * 8];
            float4 a1 = *(const float4*)&sA[kk][ty * 8 + 4];
            float4 w0 = *(const float4*)&sB[kk][tx * 8];
            float4 w1 = *(const float4*)&sB[kk][tx * 8 + 4];
            unsigned long long pa[4];
            pa[0] = pk2(a0.x, a0.y); pa[1] = pk2(a0.z, a0.w);
            pa[2] = pk2(a1.x, a1.y); pa[3] = pk2(a1.z, a1.w);
            float wv[8] = {w0.x, w0.y, w0.z, w0.w, w1.x, w1.y, w1.z, w1.w};
#pragma unroll
            for (int j = 0; j < 8; j++) {
                unsigned long long wp = pk2(wv[j], wv[j]);
#pragma unroll
                for (int p = 0; p < 4; p++) fma2(acc[p][j], pa[p], wp);
            }
        }
        __syncthreads();
    }

    float lg[8][8];
    float bias[8];
    bool valid[8];
#pragma unroll
    for (int j = 0; j < 8; j++) {
        int v = v0 + tx * 8 + j;
        valid[j] = v < V_;
        bias[j] = valid[j] ? outb[v] : 0.0f;
    }
#pragma unroll
    for (int p = 0; p < 4; p++)
#pragma unroll
        for (int j = 0; j < 8; j++) {
            float2 f = upk2(acc[p][j]);
            lg[2 * p][j]     = f.x + bias[j];
            lg[2 * p + 1][j] = f.y + bias[j];
        }
#pragma unroll
    for (int bb = 0; bb < 8; bb++) {
        int rb = ty * 8 + bb;
        float mx = -1e30f;
#pragma unroll
        for (int j = 0; j < 8; j++) {
            if (valid[j]) {
                g_logits[rb * V_ + v0 + tx * 8 + j] = lg[bb][j];
                mx = fmaxf(mx, lg[bb][j]);
            }
        }
        red[rb][tx] = mx;
    }
    __syncthreads();
    if (tid < 128) {
        float mx = red[tid][0];
#pragma unroll
        for (int i = 1; i < 16; i++) mx = fmaxf(mx, red[tid][i]);
        srm[tid] = mx;
    }
    __syncthreads();
#pragma unroll
    for (int bb = 0; bb < 8; bb++) {
        int rb = ty * 8 + bb;
        float rm = srm[rb], s = 0.0f;
#pragma unroll
        for (int j = 0; j < 8; j++)
            if (valid[j]) s += __expf(lg[bb][j] - rm);
        red[rb][tx] = s;
    }
    __syncthreads();
    if (tid < 128) {
        float s = 0.0f;
#pragma unroll
        for (int i = 0; i < 16; i++) s += red[tid][i];
        g_tmax[tid * NTILE + blockIdx.x] = srm[tid];
        g_tsum[tid * NTILE + blockIdx.x] = s;
    }
}

// =============== K11: combine tile partials -> M, scale = p_gen / S ===============
__global__ void k_combine(const float* __restrict__ outp) {
    int b = blockIdx.x, tid = threadIdx.x;          // 128
    __shared__ float red[128];
    float m = -1e30f;
    for (int i = tid; i < NTILE; i += 128) m = fmaxf(m, g_tmax[b * NTILE + i]);
    red[tid] = m; __syncthreads();
    for (int s = 64; s > 0; s >>= 1) { if (tid < s) red[tid] = fmaxf(red[tid], red[tid + s]); __syncthreads(); }
    float M = red[0]; __syncthreads();
    float sum = 0.0f;
    for (int i = tid; i < NTILE; i += 128)
        sum += g_tsum[b * NTILE + i] * __expf(g_tmax[b * NTILE + i] - M);
    red[tid] = sum; __syncthreads();
    for (int s = 64; s > 0; s >>= 1) { if (tid < s) red[tid] += red[tid + s]; __syncthreads(); }
    if (tid == 0) {
        g_M[b] = M;
        g_scale[b] = __fdividef(outp[O_PG + b], red[0]);
    }
}

// =============== K12: final vocab dist (+extra zeros) ===============
__global__ void k_final_vocab(const float* __restrict__ extra_zeros, float* __restrict__ outp) {
    int v = blockIdx.x * 256 + threadIdx.x;
    int b = blockIdx.y;
    if (v < V_) {
        outp[O_FD + b * VX_ + v] = g_scale[b] * __expf(g_logits[b * V_ + v] - g_M[b]);
    } else if (v < VX_) {
        outp[O_FD + b * VX_ + v] = extra_zeros[b * X_ + (v - V_)];
    }
}

// =============== K13: pointer scatter-add ===============
__global__ void k_scatter(const int* __restrict__ ext_vocab, float* __restrict__ outp) {
    int i = blockIdx.x * 256 + threadIdx.x;         // B*L
    int b = i >> 10;
    float pg = outp[O_PG + b];
    float av = outp[O_A + i];
    atomicAdd(&outp[O_FD + b * VX_ + ext_vocab[i]], (1.0f - pg) * av);
}

// ======================================================================
extern "C" void kernel_launch(void* const* d_in, const int* in_sizes, int n_in,
                              void* d_out, int out_size) {
    (void)in_sizes; (void)n_in; (void)out_size;
    const int*   y_t       = (const int*)d_in[0];
    const float* h0        = (const float*)d_in[1];
    const float* c0        = (const float*)d_in[2];
    const float* enc_outs  = (const float*)d_in[3];
    const float* enc_feats = (const float*)d_in[4];
    const float* mask      = (const float*)d_in[5];
    const float* c_t_1     = (const float*)d_in[6];
    const float* extra_z   = (const float*)d_in[7];
    const int*   ext_vocab = (const int*)d_in[8];
    const float* coverage  = (const float*)d_in[9];
    const float* embed_W   = (const float*)d_in[10];
    const float* Wih       = (const float*)d_in[11];
    const float* Whh       = (const float*)d_in[12];
    const float* bih       = (const float*)d_in[13];
    const float* bhh       = (const float*)d_in[14];
    const float* xctx_W    = (const float*)d_in[15];
    const float* xctx_b    = (const float*)d_in[16];
    const float* Ws_W      = (const float*)d_in[17];
    const float* Ws_b      = (const float*)d_in[18];
    const float* Wc_W      = (const float*)d_in[19];
    const float* v_W       = (const float*)d_in[20];
    const float* pgen_W    = (const float*)d_in[21];
    const float* pgen_b    = (const float*)d_in[22];
    const float* proj_W    = (const float*)d_in[23];
    const float* proj_b    = (const float*)d_in[24];
    const float* out_W     = (const float*)d_in[25];
    const float* out_b     = (const float*)d_in[26];
    float* outp = (float*)d_out;

    float* d_xT;     cudaGetSymbolAddress((void**)&d_xT, g_xT);
    float* d_gatesT; cudaGetSymbolAddress((void**)&d_gatesT, g_gatesT);
    float* d_hcT;    cudaGetSymbolAddress((void**)&d_hcT, g_hcT);
    float* d_decT;   cudaGetSymbolAddress((void**)&d_decT, g_decT);
    float* d_ctT;    cudaGetSymbolAddress((void**)&d_ctT, g_ctT);
    float* d_hidT;   cudaGetSymbolAddress((void**)&d_hidT, g_hidT);
    float* d_prepT;  cudaGetSymbolAddress((void**)&d_prepT, g_prepT);
    float* d_h0T;    cudaGetSymbolAddress((void**)&d_h0T, g_h0T);

    k_zero<<<512, 256>>>();
    k_prep<<<B_, 256>>>(y_t, c_t_1, embed_W, h0);
    // x = [c_t_1, emb] @ xctx_W.T + xctx_b   (J=128, K=640, split 5x2 chunks)
    k_gemm<<<dim3(4, 4, 5), 256>>>(d_prepT, xctx_W, 640, 640,
                                   nullptr, nullptr, 0, xctx_b, nullptr, d_xT, 2);
    // gates = x@Wih.T + h0@Whh.T + bih + bhh (J=1024, K=128+256, split 2x3)
    k_gemm<<<dim3(32, 4, 2), 256>>>(d_xT, Wih, 128, 128,
                                    d_h0T, Whh, 256, bih, bhh, d_gatesT, 3);
    k_lstm<<<128, 256>>>(c0, outp);
    // dec = [h,c]@Ws_W.T + Ws_b              (J=512, K=512, split 2x4)
    k_gemm<<<dim3(16, 4, 2), 256>>>(d_hcT, Ws_W, 512, 512,
                                    nullptr, nullptr, 0, Ws_b, nullptr, d_decT, 4);
    k_energy<<<B_ * L_ / 8, 256>>>(enc_feats, coverage, Wc_W, v_W);
    k_softmax_a<<<B_, 256>>>(mask, coverage, outp);
    k_ctx<<<dim3(16, B_), 256>>>(enc_outs, outp);
    k_finalize<<<B_, 512>>>(pgen_W, pgen_b, outp);
    // hid = [h, c_t]@proj_W.T + proj_b       (J=256, K=256+512, split 4x3)
    k_gemm<<<dim3(8, 4, 4), 256>>>(d_hcT, proj_W, 768, 256,
                                   d_ctT, proj_W + 256, 768, proj_b, nullptr, d_hidT, 3);
    k_logits<<<NTILE, 256>>>(out_W, out_b);
    k_combine<<<B_, 128>>>(outp);
    k_final_vocab<<<dim3(196, B_), 256>>>(extra_z, outp);
    k_scatter<<<B_ * L_ / 256, 256>>>(ext_vocab, outp);
}

// round 4
// speedup vs baseline: 1.7798x; 1.4459x over previous
#include <cuda_runtime.h>
#include <cuda_bf16.h>
#include <cstdint>

#define B_ 128
#define L_ 1024
#define H_ 256
#define E_ 128
#define V_ 50000
#define X_ 100
#define VX_ 50100
#define NTILE 391

// d_out float offsets (tuple order: final_dist, h, c, c_t, a, p_gen, coverage_next)
#define O_FD  0
#define O_H   6412800
#define O_C   6445568
#define O_CT  6478336
#define O_A   6543872
#define O_PG  6674944
#define O_COV 6675072

// ---------------- static device scratch (no allocations) ----------------
__device__ __align__(256) float g_prepT[640 * B_];
__device__ __align__(256) float g_h0T[256 * B_];
__device__ __align__(256) float g_xT[E_ * B_];
__device__ __align__(256) float g_gatesT[4 * H_ * B_];
__device__ __align__(256) float g_hcT[2 * H_ * B_];
__device__ __align__(256) float g_decT[2 * H_ * B_];
__device__ __align__(256) float g_ctT[2 * H_ * B_];
__device__ __align__(256) float g_hidT[H_ * B_];
__device__ __align__(256) __nv_bfloat16 g_hidB[B_ * H_];   // [b][k] bf16
__device__ __align__(256) float g_energy[B_ * L_];
__device__ __align__(256) float g_ctp[B_ * 16 * 2 * H_];
__device__ __align__(256) float g_logits[B_ * V_];
__device__ __align__(256) float g_tmax[B_ * NTILE];
__device__ __align__(256) float g_tsum[B_ * NTILE];
__device__ __align__(256) float g_M[B_];
__device__ __align__(256) float g_scale[B_];

// ---------------- helpers ----------------
__device__ __forceinline__ float fsig(float x) {
    return __fdividef(1.0f, 1.0f + __expf(-x));
}
__device__ __forceinline__ float ftanh(float x) {
    float e = __expf(2.0f * x);
    return 1.0f - __fdividef(2.0f, 1.0f + e);
}
__device__ __forceinline__ uint32_t pkbf2(float a, float b) {
    uint32_t r;
    asm("cvt.rn.bf16x2.f32 %0, %2, %1;" : "=r"(r) : "f"(a), "f"(b));
    return r;
}

// =============== K0: zero GEMM accumulators ===============
__global__ void k_zero() {
    int i = blockIdx.x * 256 + threadIdx.x;
    if (i < E_ * B_)      g_xT[i] = 0.0f;
    if (i < 4 * H_ * B_)  g_gatesT[i] = 0.0f;
    if (i < 2 * H_ * B_)  g_decT[i] = 0.0f;
    if (i < H_ * B_)      g_hidT[i] = 0.0f;
}

// =============== K0b: prep transposed activations ===============
__global__ void k_prep(const int* __restrict__ y_t, const float* __restrict__ c_t_1,
                       const float* __restrict__ embed_W, const float* __restrict__ h0) {
    int b = blockIdx.x, t = threadIdx.x;
    for (int k = t; k < 512; k += 256) g_prepT[k * 128 + b] = c_t_1[b * 512 + k];
    int y = y_t[b];
    if (t < 128) g_prepT[(512 + t) * 128 + b] = embed_W[y * 128 + t];
    if (t < 256) g_h0T[t * 128 + b] = h0[b * 256 + t];
}

// =============== unified small GEMM ===============
__global__ void __launch_bounds__(256) k_gemm(
    const float* __restrict__ actA, const float* __restrict__ WA, int sWA, int KA,
    const float* __restrict__ actB, const float* __restrict__ WB, int sWB,
    const float* __restrict__ bias1, const float* __restrict__ bias2,
    float* __restrict__ outT, int CPS)
{
    __shared__ float s_act[32][65];
    __shared__ float s_w[32][64];
    int tid = threadIdx.x;
    int lane = tid & 31, wp = tid >> 5;
    int j0 = blockIdx.x * 32;
    int b  = blockIdx.y * 32 + lane;
    int c0 = blockIdx.z * CPS;
    float acc0 = 0.0f, acc1 = 0.0f, acc2 = 0.0f, acc3 = 0.0f;

    for (int c = 0; c < CPS; c++) {
        int k0 = (c0 + c) * 64;
        const float* asrc; const float* wsrc; int ws; int kr;
        if (k0 < KA) { asrc = actA; wsrc = WA; ws = sWA; kr = k0; }
        else         { asrc = actB; wsrc = WB; ws = sWB; kr = k0 - KA; }
#pragma unroll
        for (int r = 0; r < 8; r++) {
            int k = r * 8 + wp;
            s_act[lane][k] = asrc[(kr + k) * 128 + b];
        }
        {
            int idx = tid * 2;
            int j = idx >> 4, f = (idx & 15) * 4;
            float4 v = *(const float4*)&wsrc[(j0 + j) * ws + kr + f];
            *(float4*)&s_w[j][f] = v;
            idx++;
            j = idx >> 4; f = (idx & 15) * 4;
            v = *(const float4*)&wsrc[(j0 + j) * ws + kr + f];
            *(float4*)&s_w[j][f] = v;
        }
        __syncthreads();
#pragma unroll
        for (int kk = 0; kk < 64; kk += 4) {
            float a0 = s_act[lane][kk + 0];
            float a1 = s_act[lane][kk + 1];
            float a2 = s_act[lane][kk + 2];
            float a3 = s_act[lane][kk + 3];
            float4 w0 = *(const float4*)&s_w[wp * 4 + 0][kk];
            float4 w1 = *(const float4*)&s_w[wp * 4 + 1][kk];
            float4 w2 = *(const float4*)&s_w[wp * 4 + 2][kk];
            float4 w3 = *(const float4*)&s_w[wp * 4 + 3][kk];
            acc0 += w0.x * a0 + w0.y * a1 + w0.z * a2 + w0.w * a3;
            acc1 += w1.x * a0 + w1.y * a1 + w1.z * a2 + w1.w * a3;
            acc2 += w2.x * a0 + w2.y * a1 + w2.z * a2 + w2.w * a3;
            acc3 += w3.x * a0 + w3.y * a1 + w3.z * a2 + w3.w * a3;
        }
        __syncthreads();
    }
    int j = j0 + wp * 4;
    if (blockIdx.z == 0 && bias1) {
        acc0 += bias1[j + 0]; acc1 += bias1[j + 1]; acc2 += bias1[j + 2]; acc3 += bias1[j + 3];
        if (bias2) {
            acc0 += bias2[j + 0]; acc1 += bias2[j + 1]; acc2 += bias2[j + 2]; acc3 += bias2[j + 3];
        }
    }
    atomicAdd(&outT[(j + 0) * 128 + b], acc0);
    atomicAdd(&outT[(j + 1) * 128 + b], acc1);
    atomicAdd(&outT[(j + 2) * 128 + b], acc2);
    atomicAdd(&outT[(j + 3) * 128 + b], acc3);
}

// =============== K3: LSTM pointwise ===============
__global__ void k_lstm(const float* __restrict__ c0, float* __restrict__ outp) {
    int i = blockIdx.x * 256 + threadIdx.x;
    int t = i >> 7, b = i & 127;
    float gi = g_gatesT[i];
    float gf = g_gatesT[i + 32768];
    float gg = g_gatesT[i + 65536];
    float go = g_gatesT[i + 98304];
    float c0v = c0[b * 256 + t];
    float cc = fsig(gf) * c0v + fsig(gi) * ftanh(gg);
    float hh = fsig(go) * ftanh(cc);
    outp[O_H + b * 256 + t] = hh;
    outp[O_C + b * 256 + t] = cc;
    g_hcT[t * 128 + b] = hh;
    g_hcT[(256 + t) * 128 + b] = cc;
}

// =============== K5: attention energy (streams enc_feats) ===============
__global__ void k_energy(const float* __restrict__ enc_feats,
                         const float* __restrict__ coverage,
                         const float* __restrict__ Wc_W, const float* __restrict__ v_W) {
    int idx0 = blockIdx.x * 8;
    int b = idx0 >> 10;
    __shared__ float sdec[512], swc[512], sv[512];
    int tid = threadIdx.x;
    for (int i = tid; i < 512; i += 256) {
        sdec[i] = g_decT[i * 128 + b];
        swc[i]  = Wc_W[i];
        sv[i]   = v_W[i];
    }
    __syncthreads();
    int w = tid >> 5, lane = tid & 31;
    int idx = idx0 + w;
    float cov = coverage[idx];
    const float* base = enc_feats + (size_t)idx * 512;
    float e = 0.0f;
#pragma unroll
    for (int c = 0; c < 4; c++) {
        int d0 = c * 128 + lane * 4;
        float4 f  = *(const float4*)(base + d0);
        float4 dv = *(const float4*)(sdec + d0);
        float4 wv = *(const float4*)(swc + d0);
        float4 vv = *(const float4*)(sv + d0);
        e += ftanh(f.x + dv.x + cov * wv.x) * vv.x;
        e += ftanh(f.y + dv.y + cov * wv.y) * vv.y;
        e += ftanh(f.z + dv.z + cov * wv.z) * vv.z;
        e += ftanh(f.w + dv.w + cov * wv.w) * vv.w;
    }
#pragma unroll
    for (int o = 16; o; o >>= 1) e += __shfl_xor_sync(0xffffffffu, e, o);
    if (lane == 0) g_energy[idx] = e;
}

// =============== K6: softmax over L ===============
__global__ void k_softmax_a(const float* __restrict__ mask, const float* __restrict__ coverage,
                            float* __restrict__ outp) {
    int b = blockIdx.x, tid = threadIdx.x;
    __shared__ float red[256];
    float e[4];
#pragma unroll
    for (int j = 0; j < 4; j++) e[j] = g_energy[b * 1024 + tid + j * 256];
    float m = fmaxf(fmaxf(e[0], e[1]), fmaxf(e[2], e[3]));
    red[tid] = m; __syncthreads();
    for (int s = 128; s > 0; s >>= 1) { if (tid < s) red[tid] = fmaxf(red[tid], red[tid + s]); __syncthreads(); }
    float M = red[0]; __syncthreads();
    float ev[4], sum = 0.0f;
#pragma unroll
    for (int j = 0; j < 4; j++) {
        ev[j] = __expf(e[j] - M) * mask[b * 1024 + tid + j * 256];
        sum += ev[j];
    }
    red[tid] = sum; __syncthreads();
    for (int s = 128; s > 0; s >>= 1) { if (tid < s) red[tid] += red[tid + s]; __syncthreads(); }
    float inv = __fdividef(1.0f, red[0]);
#pragma unroll
    for (int j = 0; j < 4; j++) {
        int i = b * 1024 + tid + j * 256;
        float a = ev[j] * inv;
        outp[O_A + i] = a;
        outp[O_COV + i] = coverage[i] + a;
    }
}

// =============== K7: c_t partials (streams enc_outs) ===============
__global__ void k_ctx(const float* __restrict__ enc_outs, const float* __restrict__ outp) {
    int chunk = blockIdx.x, b = blockIdx.y;
    __shared__ float sa[64];
    int tid = threadIdx.x;
    if (tid < 64) sa[tid] = outp[O_A + b * 1024 + chunk * 64 + tid];
    __syncthreads();
    const float2* p = (const float2*)(enc_outs + ((size_t)b * 1024 + chunk * 64) * 512);
    float2 acc = make_float2(0.0f, 0.0f);
#pragma unroll 8
    for (int i = 0; i < 64; i++) {
        float2 v = p[i * 256 + tid];
        float a = sa[i];
        acc.x += a * v.x;
        acc.y += a * v.y;
    }
    *(float2*)&g_ctp[(b * 16 + chunk) * 512 + 2 * tid] = acc;
}

// =============== K8: reduce c_t, p_gen ===============
__global__ void k_finalize(const float* __restrict__ pgen_W, const float* __restrict__ pgen_b,
                           float* __restrict__ outp) {
    int b = blockIdx.x, tid = threadIdx.x;
    __shared__ float sct[512];
    __shared__ float red[512];
    float s = 0.0f;
#pragma unroll
    for (int ch = 0; ch < 16; ch++) s += g_ctp[(b * 16 + ch) * 512 + tid];
    sct[tid] = s;
    outp[O_CT + b * 512 + tid] = s;
    g_ctT[tid * 128 + b] = s;
    __syncthreads();
    float p = pgen_W[tid] * sct[tid];
    float z2 = (tid < 256) ? outp[O_H + b * 256 + tid] : outp[O_C + b * 256 + (tid - 256)];
    p += pgen_W[512 + tid] * z2;
    if (tid < 128) p += pgen_W[1024 + tid] * g_xT[tid * 128 + b];
    red[tid] = p; __syncthreads();
    for (int st = 256; st > 0; st >>= 1) { if (tid < st) red[tid] += red[tid + st]; __syncthreads(); }
    if (tid == 0) outp[O_PG + b] = fsig(red[0] + pgen_b[0]);
}

// =============== K9b: hid -> bf16 [b][k] ===============
__global__ void k_hid2bf16() {
    int i = blockIdx.x * 256 + threadIdx.x;     // 32768
    int k = i >> 7, b = i & 127;
    g_hidB[b * 256 + k] = __float2bfloat16(g_hidT[i]);
}

// =============== K10: logits GEMM on tensor cores (bf16 mma.sync) ===============
// tile: 128 b x 128 v, K=256 in 8 chunks of 32. 8 warps: wm(2) x wn(4).
__global__ void __launch_bounds__(256) k_logits_mma(const float* __restrict__ outW,
                                                    const float* __restrict__ outb) {
    const int v0 = blockIdx.x * 128;
    __shared__ __align__(16) uint32_t sA[128 * 17];   // [b][17 words] (32 bf16 + pad)
    __shared__ __align__(16) uint32_t sB[128 * 17];   // [v][17 words]
    __shared__ float s_bias[128];
    __shared__ float s_red[128][4];
    __shared__ float s_rowmax[128];
    int tid = threadIdx.x;
    int lane = tid & 31, wid = tid >> 5;
    int wm = wid >> 2, wn = wid & 3;
    int g = lane >> 2, tg = lane & 3;

    if (tid < 128) {
        int v = v0 + tid;
        s_bias[tid] = (v < V_) ? outb[v] : 0.0f;
    }

    float acc[4][4][4];
#pragma unroll
    for (int mt = 0; mt < 4; mt++)
#pragma unroll
        for (int nt = 0; nt < 4; nt++)
#pragma unroll
            for (int q = 0; q < 4; q++) acc[mt][nt][q] = 0.0f;

    const uint32_t* hidW = (const uint32_t*)g_hidB;   // [b][128 words]

    for (int k0 = 0; k0 < 256; k0 += 32) {
        // stage A: 128 b x 16 words
#pragma unroll
        for (int r = 0; r < 8; r++) {
            int idx = r * 256 + tid;
            int b = idx >> 4, w = idx & 15;
            sA[b * 17 + w] = hidW[b * 128 + (k0 >> 1) + w];
        }
        // stage B: 128 v rows, fp32->bf16 convert
#pragma unroll
        for (int r = 0; r < 4; r++) {
            int idx = r * 256 + tid;
            int v = idx >> 3, f = idx & 7;
            float4 w4 = make_float4(0.f, 0.f, 0.f, 0.f);
            if (v0 + v < V_) w4 = *(const float4*)&outW[(size_t)(v0 + v) * 256 + k0 + f * 4];
            sB[v * 17 + f * 2]     = pkbf2(w4.x, w4.y);
            sB[v * 17 + f * 2 + 1] = pkbf2(w4.z, w4.w);
        }
        __syncthreads();
#pragma unroll
        for (int kk = 0; kk < 2; kk++) {
            int kw = kk * 8 + tg;
            uint32_t a[4][4];
#pragma unroll
            for (int mt = 0; mt < 4; mt++) {
                int r0 = wm * 64 + mt * 16 + g;
                a[mt][0] = sA[r0 * 17 + kw];
                a[mt][1] = sA[(r0 + 8) * 17 + kw];
                a[mt][2] = sA[r0 * 17 + kw + 4];
                a[mt][3] = sA[(r0 + 8) * 17 + kw + 4];
            }
#pragma unroll
            for (int nt = 0; nt < 4; nt++) {
                int n0 = wn * 32 + nt * 8 + g;
                uint32_t b0 = sB[n0 * 17 + kw];
                uint32_t b1 = sB[n0 * 17 + kw + 4];
#pragma unroll
                for (int mt = 0; mt < 4; mt++) {
                    asm volatile(
                        "mma.sync.aligned.m16n8k16.row.col.f32.bf16.bf16.f32 "
                        "{%0,%1,%2,%3},{%4,%5,%6,%7},{%8,%9},{%0,%1,%2,%3};"
                        : "+f"(acc[mt][nt][0]), "+f"(acc[mt][nt][1]),
                          "+f"(acc[mt][nt][2]), "+f"(acc[mt][nt][3])
                        : "r"(a[mt][0]), "r"(a[mt][1]), "r"(a[mt][2]), "r"(a[mt][3]),
                          "r"(b0), "r"(b1));
                }
            }
        }
        __syncthreads();
    }

    // ---- epilogue: bias, store logits, per-row max/sumexp over this 128-col tile ----
    int cbase = wn * 32 + tg * 2;          // col of frag element 0
    bool val[4];
#pragma unroll
    for (int nt = 0; nt < 4; nt++) val[nt] = (v0 + cbase + nt * 8) < V_;
#pragma unroll
    for (int mt = 0; mt < 4; mt++)
#pragma unroll
        for (int nt = 0; nt < 4; nt++) {
            float bv0 = s_bias[cbase + nt * 8];
            float bv1 = s_bias[cbase + nt * 8 + 1];
            acc[mt][nt][0] += bv0; acc[mt][nt][1] += bv1;
            acc[mt][nt][2] += bv0; acc[mt][nt][3] += bv1;
        }
    // store logits + per-thread row max
#pragma unroll
    for (int mt = 0; mt < 4; mt++) {
#pragma unroll
        for (int h = 0; h < 2; h++) {
            int row = wm * 64 + mt * 16 + g + h * 8;
            float mx = -1e30f;
#pragma unroll
            for (int nt = 0; nt < 4; nt++) {
                if (val[nt]) {
                    float e0 = acc[mt][nt][2 * h], e1 = acc[mt][nt][2 * h + 1];
                    *(float2*)&g_logits[(size_t)row * V_ + v0 + cbase + nt * 8] = make_float2(e0, e1);
                    mx = fmaxf(mx, fmaxf(e0, e1));
                }
            }
            mx = fmaxf(mx, __shfl_xor_sync(0xffffffffu, mx, 1));
            mx = fmaxf(mx, __shfl_xor_sync(0xffffffffu, mx, 2));
            if (tg == 0) s_red[row][wn] = mx;
        }
    }
    __syncthreads();
    if (tid < 128)
        s_rowmax[tid] = fmaxf(fmaxf(s_red[tid][0], s_red[tid][1]),
                              fmaxf(s_red[tid][2], s_red[tid][3]));
    __syncthreads();
#pragma unroll
    for (int mt = 0; mt < 4; mt++) {
#pragma unroll
        for (int h = 0; h < 2; h++) {
            int row = wm * 64 + mt * 16 + g + h * 8;
            float rm = s_rowmax[row], s = 0.0f;
#pragma unroll
            for (int nt = 0; nt < 4; nt++) {
                if (val[nt]) {
                    s += __expf(acc[mt][nt][2 * h] - rm);
                    s += __expf(acc[mt][nt][2 * h + 1] - rm);
                }
            }
            s += __shfl_xor_sync(0xffffffffu, s, 1);
            s += __shfl_xor_sync(0xffffffffu, s, 2);
            if (tg == 0) s_red[row][wn] = s;
        }
    }
    __syncthreads();
    if (tid < 128) {
        float s = s_red[tid][0] + s_red[tid][1] + s_red[tid][2] + s_red[tid][3];
        g_tmax[tid * NTILE + blockIdx.x] = s_rowmax[tid];
        g_tsum[tid * NTILE + blockIdx.x] = s;
    }
}

// =============== K11: combine tile partials ===============
__global__ void k_combine(const float* __restrict__ outp) {
    int b = blockIdx.x, tid = threadIdx.x;
    __shared__ float red[128];
    float m = -1e30f;
    for (int i = tid; i < NTILE; i += 128) m = fmaxf(m, g_tmax[b * NTILE + i]);
    red[tid] = m; __syncthreads();
    for (int s = 64; s > 0; s >>= 1) { if (tid < s) red[tid] = fmaxf(red[tid], red[tid + s]); __syncthreads(); }
    float M = red[0]; __syncthreads();
    float sum = 0.0f;
    for (int i = tid; i < NTILE; i += 128)
        sum += g_tsum[b * NTILE + i] * __expf(g_tmax[b * NTILE + i] - M);
    red[tid] = sum; __syncthreads();
    for (int s = 64; s > 0; s >>= 1) { if (tid < s) red[tid] += red[tid + s]; __syncthreads(); }
    if (tid == 0) {
        g_M[b] = M;
        g_scale[b] = __fdividef(outp[O_PG + b], red[0]);
    }
}

// =============== K12: final vocab dist ===============
__global__ void k_final_vocab(const float* __restrict__ extra_zeros, float* __restrict__ outp) {
    int v = blockIdx.x * 256 + threadIdx.x;
    int b = blockIdx.y;
    if (v < V_) {
        outp[O_FD + b * VX_ + v] = g_scale[b] * __expf(g_logits[b * V_ + v] - g_M[b]);
    } else if (v < VX_) {
        outp[O_FD + b * VX_ + v] = extra_zeros[b * X_ + (v - V_)];
    }
}

// =============== K13: pointer scatter-add ===============
__global__ void k_scatter(const int* __restrict__ ext_vocab, float* __restrict__ outp) {
    int i = blockIdx.x * 256 + threadIdx.x;
    int b = i >> 10;
    float pg = outp[O_PG + b];
    float av = outp[O_A + i];
    atomicAdd(&outp[O_FD + b * VX_ + ext_vocab[i]], (1.0f - pg) * av);
}

// ======================================================================
extern "C" void kernel_launch(void* const* d_in, const int* in_sizes, int n_in,
                              void* d_out, int out_size) {
    (void)in_sizes; (void)n_in; (void)out_size;
    const int*   y_t       = (const int*)d_in[0];
    const float* h0        = (const float*)d_in[1];
    const float* c0        = (const float*)d_in[2];
    const float* enc_outs  = (const float*)d_in[3];
    const float* enc_feats = (const float*)d_in[4];
    const float* mask      = (const float*)d_in[5];
    const float* c_t_1     = (const float*)d_in[6];
    const float* extra_z   = (const float*)d_in[7];
    const int*   ext_vocab = (const int*)d_in[8];
    const float* coverage  = (const float*)d_in[9];
    const float* embed_W   = (const float*)d_in[10];
    const float* Wih       = (const float*)d_in[11];
    const float* Whh       = (const float*)d_in[12];
    const float* bih       = (const float*)d_in[13];
    const float* bhh       = (const float*)d_in[14];
    const float* xctx_W    = (const float*)d_in[15];
    const float* xctx_b    = (const float*)d_in[16];
    const float* Ws_W      = (const float*)d_in[17];
    const float* Ws_b      = (const float*)d_in[18];
    const float* Wc_W      = (const float*)d_in[19];
    const float* v_W       = (const float*)d_in[20];
    const float* pgen_W    = (const float*)d_in[21];
    const float* pgen_b    = (const float*)d_in[22];
    const float* proj_W    = (const float*)d_in[23];
    const float* proj_b    = (const float*)d_in[24];
    const float* out_W     = (const float*)d_in[25];
    const float* out_b     = (const float*)d_in[26];
    float* outp = (float*)d_out;

    float* d_xT;     cudaGetSymbolAddress((void**)&d_xT, g_xT);
    float* d_gatesT; cudaGetSymbolAddress((void**)&d_gatesT, g_gatesT);
    float* d_hcT;    cudaGetSymbolAddress((void**)&d_hcT, g_hcT);
    float* d_decT;   cudaGetSymbolAddress((void**)&d_decT, g_decT);
    float* d_ctT;    cudaGetSymbolAddress((void**)&d_ctT, g_ctT);
    float* d_hidT;   cudaGetSymbolAddress((void**)&d_hidT, g_hidT);
    float* d_prepT;  cudaGetSymbolAddress((void**)&d_prepT, g_prepT);
    float* d_h0T;    cudaGetSymbolAddress((void**)&d_h0T, g_h0T);

    k_zero<<<512, 256>>>();
    k_prep<<<B_, 256>>>(y_t, c_t_1, embed_W, h0);
    k_gemm<<<dim3(4, 4, 5), 256>>>(d_prepT, xctx_W, 640, 640,
                                   nullptr, nullptr, 0, xctx_b, nullptr, d_xT, 2);
    k_gemm<<<dim3(32, 4, 2), 256>>>(d_xT, Wih, 128, 128,
                                    d_h0T, Whh, 256, bih, bhh, d_gatesT, 3);
    k_lstm<<<128, 256>>>(c0, outp);
    k_gemm<<<dim3(16, 4, 2), 256>>>(d_hcT, Ws_W, 512, 512,
                                    nullptr, nullptr, 0, Ws_b, nullptr, d_decT, 4);
    k_energy<<<B_ * L_ / 8, 256>>>(enc_feats, coverage, Wc_W, v_W);
    k_softmax_a<<<B_, 256>>>(mask, coverage, outp);
    k_ctx<<<dim3(16, B_), 256>>>(enc_outs, outp);
    k_finalize<<<B_, 512>>>(pgen_W, pgen_b, outp);
    k_gemm<<<dim3(8, 4, 4), 256>>>(d_hcT, proj_W, 768, 256,
                                   d_ctT, proj_W + 256, 768, proj_b, nullptr, d_hidT, 3);
    k_hid2bf16<<<128, 256>>>();
    k_logits_mma<<<NTILE, 256>>>(out_W, out_b);
    k_combine<<<B_, 128>>>(outp);
    k_final_vocab<<<dim3(196, B_), 256>>>(extra_z, outp);
    k_scatter<<<B_ * L_ / 256, 256>>>(ext_vocab, outp);
}

// round 5
// speedup vs baseline: 1.8573x; 1.0436x over previous
#include <cuda_runtime.h>
#include <cuda_bf16.h>
#include <cstdint>

#define B_ 128
#define L_ 1024
#define H_ 256
#define E_ 128
#define V_ 50000
#define X_ 100
#define VX_ 50100
#define NTILE 391

// d_out float offsets (tuple order: final_dist, h, c, c_t, a, p_gen, coverage_next)
#define O_FD  0
#define O_H   6412800
#define O_C   6445568
#define O_CT  6478336
#define O_A   6543872
#define O_PG  6674944
#define O_COV 6675072

// ---------------- static device scratch (no allocations) ----------------
__device__ __align__(256) float g_prepT[640 * B_];
__device__ __align__(256) float g_h0T[256 * B_];
__device__ __align__(256) float g_xT[E_ * B_];
__device__ __align__(256) float g_gatesT[4 * H_ * B_];
__device__ __align__(256) float g_hcT[2 * H_ * B_];
__device__ __align__(256) float g_decT[2 * H_ * B_];
__device__ __align__(256) float g_ctT[2 * H_ * B_];
__device__ __align__(256) float g_hidT[H_ * B_];          // [k][b]
__device__ __align__(256) float g_energy[B_ * L_];
__device__ __align__(256) float g_ctp[B_ * 16 * 2 * H_];
__device__ __align__(256) float g_logits[B_ * V_];
__device__ __align__(256) float g_tmax[B_ * NTILE];
__device__ __align__(256) float g_tsum[B_ * NTILE];
__device__ __align__(256) float g_M[B_];
__device__ __align__(256) float g_scale[B_];

// ---------------- helpers ----------------
__device__ __forceinline__ float fsig(float x) {
    return __fdividef(1.0f, 1.0f + __expf(-x));
}
__device__ __forceinline__ float ftanh(float x) {
    float e = __expf(2.0f * x);
    return 1.0f - __fdividef(2.0f, 1.0f + e);
}
__device__ __forceinline__ uint32_t pkbf2(float a, float b) {
    uint32_t r;
    asm("cvt.rn.bf16x2.f32 %0, %2, %1;" : "=r"(r) : "f"(a), "f"(b));
    return r;
}

// =============== K0: zero GEMM accumulators ===============
__global__ void k_zero() {
    int i = blockIdx.x * 256 + threadIdx.x;
    if (i < E_ * B_)      g_xT[i] = 0.0f;
    if (i < 4 * H_ * B_)  g_gatesT[i] = 0.0f;
    if (i < 2 * H_ * B_)  g_decT[i] = 0.0f;
    if (i < H_ * B_)      g_hidT[i] = 0.0f;
}

// =============== K0b: prep transposed activations ===============
__global__ void k_prep(const int* __restrict__ y_t, const float* __restrict__ c_t_1,
                       const float* __restrict__ embed_W, const float* __restrict__ h0) {
    int b = blockIdx.x, t = threadIdx.x;
    for (int k = t; k < 512; k += 256) g_prepT[k * 128 + b] = c_t_1[b * 512 + k];
    int y = y_t[b];
    if (t < 128) g_prepT[(512 + t) * 128 + b] = embed_W[y * 128 + t];
    if (t < 256) g_h0T[t * 128 + b] = h0[b * 256 + t];
}

// =============== unified small GEMM (1 chunk of 64 k per block) ===============
// outT[j][b] += sum_k act[k][b] * W[j][k]  (+bias on z==0)
__global__ void __launch_bounds__(256) k_gemm(
    const float* __restrict__ actA, const float* __restrict__ WA, int sWA, int KA,
    const float* __restrict__ actB, const float* __restrict__ WB, int sWB,
    const float* __restrict__ bias1, const float* __restrict__ bias2,
    float* __restrict__ outT)
{
    __shared__ float s_act[32][65];
    __shared__ float s_w[32][64];
    int tid = threadIdx.x;
    int lane = tid & 31, wp = tid >> 5;
    int j0 = blockIdx.x * 32;
    int b  = blockIdx.y * 32 + lane;
    int k0 = blockIdx.z * 64;

    const float* asrc; const float* wsrc; int ws; int kr;
    if (k0 < KA) { asrc = actA; wsrc = WA; ws = sWA; kr = k0; }
    else         { asrc = actB; wsrc = WB; ws = sWB; kr = k0 - KA; }
#pragma unroll
    for (int r = 0; r < 8; r++) {
        int k = r * 8 + wp;
        s_act[lane][k] = asrc[(kr + k) * 128 + b];
    }
    {
        int idx = tid * 2;
        int j = idx >> 4, f = (idx & 15) * 4;
        float4 v = *(const float4*)&wsrc[(j0 + j) * ws + kr + f];
        *(float4*)&s_w[j][f] = v;
        idx++;
        j = idx >> 4; f = (idx & 15) * 4;
        v = *(const float4*)&wsrc[(j0 + j) * ws + kr + f];
        *(float4*)&s_w[j][f] = v;
    }
    __syncthreads();
    float acc0 = 0.0f, acc1 = 0.0f, acc2 = 0.0f, acc3 = 0.0f;
#pragma unroll
    for (int kk = 0; kk < 64; kk += 4) {
        float a0 = s_act[lane][kk + 0];
        float a1 = s_act[lane][kk + 1];
        float a2 = s_act[lane][kk + 2];
        float a3 = s_act[lane][kk + 3];
        float4 w0 = *(const float4*)&s_w[wp * 4 + 0][kk];
        float4 w1 = *(const float4*)&s_w[wp * 4 + 1][kk];
        float4 w2 = *(const float4*)&s_w[wp * 4 + 2][kk];
        float4 w3 = *(const float4*)&s_w[wp * 4 + 3][kk];
        acc0 += w0.x * a0 + w0.y * a1 + w0.z * a2 + w0.w * a3;
        acc1 += w1.x * a0 + w1.y * a1 + w1.z * a2 + w1.w * a3;
        acc2 += w2.x * a0 + w2.y * a1 + w2.z * a2 + w2.w * a3;
        acc3 += w3.x * a0 + w3.y * a1 + w3.z * a2 + w3.w * a3;
    }
    int j = j0 + wp * 4;
    if (blockIdx.z == 0 && bias1) {
        acc0 += bias1[j + 0]; acc1 += bias1[j + 1]; acc2 += bias1[j + 2]; acc3 += bias1[j + 3];
        if (bias2) {
            acc0 += bias2[j + 0]; acc1 += bias2[j + 1]; acc2 += bias2[j + 2]; acc3 += bias2[j + 3];
        }
    }
    atomicAdd(&outT[(j + 0) * 128 + b], acc0);
    atomicAdd(&outT[(j + 1) * 128 + b], acc1);
    atomicAdd(&outT[(j + 2) * 128 + b], acc2);
    atomicAdd(&outT[(j + 3) * 128 + b], acc3);
}

// =============== K3: LSTM pointwise ===============
__global__ void k_lstm(const float* __restrict__ c0, float* __restrict__ outp) {
    int i = blockIdx.x * 256 + threadIdx.x;
    int t = i >> 7, b = i & 127;
    float gi = g_gatesT[i];
    float gf = g_gatesT[i + 32768];
    float gg = g_gatesT[i + 65536];
    float go = g_gatesT[i + 98304];
    float c0v = c0[b * 256 + t];
    float cc = fsig(gf) * c0v + fsig(gi) * ftanh(gg);
    float hh = fsig(go) * ftanh(cc);
    outp[O_H + b * 256 + t] = hh;
    outp[O_C + b * 256 + t] = cc;
    g_hcT[t * 128 + b] = hh;
    g_hcT[(256 + t) * 128 + b] = cc;
}

// =============== K5: attention energy (streams enc_feats) ===============
__global__ void k_energy(const float* __restrict__ enc_feats,
                         const float* __restrict__ coverage,
                         const float* __restrict__ Wc_W, const float* __restrict__ v_W) {
    int idx0 = blockIdx.x * 8;
    int b = idx0 >> 10;
    __shared__ float sdec[512], swc[512], sv[512];
    int tid = threadIdx.x;
    for (int i = tid; i < 512; i += 256) {
        sdec[i] = g_decT[i * 128 + b];
        swc[i]  = Wc_W[i];
        sv[i]   = v_W[i];
    }
    __syncthreads();
    int w = tid >> 5, lane = tid & 31;
    int idx = idx0 + w;
    float cov = coverage[idx];
    const float* base = enc_feats + (size_t)idx * 512;
    float e = 0.0f;
#pragma unroll
    for (int c = 0; c < 4; c++) {
        int d0 = c * 128 + lane * 4;
        float4 f  = *(const float4*)(base + d0);
        float4 dv = *(const float4*)(sdec + d0);
        float4 wv = *(const float4*)(swc + d0);
        float4 vv = *(const float4*)(sv + d0);
        e += ftanh(f.x + dv.x + cov * wv.x) * vv.x;
        e += ftanh(f.y + dv.y + cov * wv.y) * vv.y;
        e += ftanh(f.z + dv.z + cov * wv.z) * vv.z;
        e += ftanh(f.w + dv.w + cov * wv.w) * vv.w;
    }
#pragma unroll
    for (int o = 16; o; o >>= 1) e += __shfl_xor_sync(0xffffffffu, e, o);
    if (lane == 0) g_energy[idx] = e;
}

// =============== K6: softmax over L ===============
__global__ void k_softmax_a(const float* __restrict__ mask, const float* __restrict__ coverage,
                            float* __restrict__ outp) {
    int b = blockIdx.x, tid = threadIdx.x;
    __shared__ float red[256];
    float e[4];
#pragma unroll
    for (int j = 0; j < 4; j++) e[j] = g_energy[b * 1024 + tid + j * 256];
    float m = fmaxf(fmaxf(e[0], e[1]), fmaxf(e[2], e[3]));
    red[tid] = m; __syncthreads();
    for (int s = 128; s > 0; s >>= 1) { if (tid < s) red[tid] = fmaxf(red[tid], red[tid + s]); __syncthreads(); }
    float M = red[0]; __syncthreads();
    float ev[4], sum = 0.0f;
#pragma unroll
    for (int j = 0; j < 4; j++) {
        ev[j] = __expf(e[j] - M) * mask[b * 1024 + tid + j * 256];
        sum += ev[j];
    }
    red[tid] = sum; __syncthreads();
    for (int s = 128; s > 0; s >>= 1) { if (tid < s) red[tid] += red[tid + s]; __syncthreads(); }
    float inv = __fdividef(1.0f, red[0]);
#pragma unroll
    for (int j = 0; j < 4; j++) {
        int i = b * 1024 + tid + j * 256;
        float a = ev[j] * inv;
        outp[O_A + i] = a;
        outp[O_COV + i] = coverage[i] + a;
    }
}

// =============== K7: c_t partials (streams enc_outs) ===============
__global__ void k_ctx(const float* __restrict__ enc_outs, const float* __restrict__ outp) {
    int chunk = blockIdx.x, b = blockIdx.y;
    __shared__ float sa[64];
    int tid = threadIdx.x;
    if (tid < 64) sa[tid] = outp[O_A + b * 1024 + chunk * 64 + tid];
    __syncthreads();
    const float2* p = (const float2*)(enc_outs + ((size_t)b * 1024 + chunk * 64) * 512);
    float2 acc = make_float2(0.0f, 0.0f);
#pragma unroll 8
    for (int i = 0; i < 64; i++) {
        float2 v = p[i * 256 + tid];
        float a = sa[i];
        acc.x += a * v.x;
        acc.y += a * v.y;
    }
    *(float2*)&g_ctp[(b * 16 + chunk) * 512 + 2 * tid] = acc;
}

// =============== K8: reduce c_t, p_gen ===============
__global__ void k_finalize(const float* __restrict__ pgen_W, const float* __restrict__ pgen_b,
                           float* __restrict__ outp) {
    int b = blockIdx.x, tid = threadIdx.x;
    __shared__ float sct[512];
    __shared__ float red[512];
    float s = 0.0f;
#pragma unroll
    for (int ch = 0; ch < 16; ch++) s += g_ctp[(b * 16 + ch) * 512 + tid];
    sct[tid] = s;
    outp[O_CT + b * 512 + tid] = s;
    g_ctT[tid * 128 + b] = s;
    __syncthreads();
    float p = pgen_W[tid] * sct[tid];
    float z2 = (tid < 256) ? outp[O_H + b * 256 + tid] : outp[O_C + b * 256 + (tid - 256)];
    p += pgen_W[512 + tid] * z2;
    if (tid < 128) p += pgen_W[1024 + tid] * g_xT[tid * 128 + b];
    red[tid] = p; __syncthreads();
    for (int st = 256; st > 0; st >>= 1) { if (tid < st) red[tid] += red[tid + st]; __syncthreads(); }
    if (tid == 0) outp[O_PG + b] = fsig(red[0] + pgen_b[0]);
}

// =============== K10: logits GEMM on tensor cores (bf16 mma.sync) ===============
// tile: 128 b x 128 v, K=256 in 8 chunks of 32. 8 warps: wm(2) x wn(4).
// A staged from fp32 g_hidT [k][b] with in-flight bf16 conversion.
__global__ void __launch_bounds__(256) k_logits_mma(const float* __restrict__ outW,
                                                    const float* __restrict__ outb) {
    const int v0 = blockIdx.x * 128;
    __shared__ __align__(16) uint32_t sA[128 * 17];   // [b][17 words] (32 bf16 + pad)
    __shared__ __align__(16) uint32_t sB[128 * 17];   // [v][17 words]
    __shared__ float s_bias[128];
    __shared__ float s_red[128][4];
    __shared__ float s_rowmax[128];
    int tid = threadIdx.x;
    int lane = tid & 31, wid = tid >> 5;
    int wm = wid >> 2, wn = wid & 3;
    int g = lane >> 2, tg = lane & 3;

    if (tid < 128) {
        int v = v0 + tid;
        s_bias[tid] = (v < V_) ? outb[v] : 0.0f;
    }

    float acc[4][4][4];
#pragma unroll
    for (int mt = 0; mt < 4; mt++)
#pragma unroll
        for (int nt = 0; nt < 4; nt++)
#pragma unroll
            for (int q = 0; q < 4; q++) acc[mt][nt][q] = 0.0f;

    for (int k0 = 0; k0 < 256; k0 += 32) {
        // stage A: convert fp32 hidT[k][b] -> bf16x2 sA[b][w]; tid-fast over b (coalesced)
#pragma unroll
        for (int r = 0; r < 8; r++) {
            int idx = r * 256 + tid;
            int b = idx & 127, w = idx >> 7;      // w in 0..15
            float lo = g_hidT[(k0 + 2 * w) * 128 + b];
            float hi = g_hidT[(k0 + 2 * w + 1) * 128 + b];
            sA[b * 17 + w] = pkbf2(lo, hi);
        }
        // stage B: 128 v rows, fp32->bf16 convert
#pragma unroll
        for (int r = 0; r < 4; r++) {
            int idx = r * 256 + tid;
            int v = idx >> 3, f = idx & 7;
            float4 w4 = make_float4(0.f, 0.f, 0.f, 0.f);
            if (v0 + v < V_) w4 = *(const float4*)&outW[(size_t)(v0 + v) * 256 + k0 + f * 4];
            sB[v * 17 + f * 2]     = pkbf2(w4.x, w4.y);
            sB[v * 17 + f * 2 + 1] = pkbf2(w4.z, w4.w);
        }
        __syncthreads();
#pragma unroll
        for (int kk = 0; kk < 2; kk++) {
            int kw = kk * 8 + tg;
            uint32_t a[4][4];
#pragma unroll
            for (int mt = 0; mt < 4; mt++) {
                int r0 = wm * 64 + mt * 16 + g;
                a[mt][0] = sA[r0 * 17 + kw];
                a[mt][1] = sA[(r0 + 8) * 17 + kw];
                a[mt][2] = sA[r0 * 17 + kw + 4];
                a[mt][3] = sA[(r0 + 8) * 17 + kw + 4];
            }
#pragma unroll
            for (int nt = 0; nt < 4; nt++) {
                int n0 = wn * 32 + nt * 8 + g;
                uint32_t b0 = sB[n0 * 17 + kw];
                uint32_t b1 = sB[n0 * 17 + kw + 4];
#pragma unroll
                for (int mt = 0; mt < 4; mt++) {
                    asm volatile(
                        "mma.sync.aligned.m16n8k16.row.col.f32.bf16.bf16.f32 "
                        "{%0,%1,%2,%3},{%4,%5,%6,%7},{%8,%9},{%0,%1,%2,%3};"
                        : "+f"(acc[mt][nt][0]), "+f"(acc[mt][nt][1]),
                          "+f"(acc[mt][nt][2]), "+f"(acc[mt][nt][3])
                        : "r"(a[mt][0]), "r"(a[mt][1]), "r"(a[mt][2]), "r"(a[mt][3]),
                          "r"(b0), "r"(b1));
                }
            }
        }
        __syncthreads();
    }

    // ---- epilogue: bias, store logits, per-row max/sumexp over this 128-col tile ----
    int cbase = wn * 32 + tg * 2;
    bool val[4];
#pragma unroll
    for (int nt = 0; nt < 4; nt++) val[nt] = (v0 + cbase + nt * 8) < V_;
#pragma unroll
    for (int mt = 0; mt < 4; mt++)
#pragma unroll
        for (int nt = 0; nt < 4; nt++) {
            float bv0 = s_bias[cbase + nt * 8];
            float bv1 = s_bias[cbase + nt * 8 + 1];
            acc[mt][nt][0] += bv0; acc[mt][nt][1] += bv1;
            acc[mt][nt][2] += bv0; acc[mt][nt][3] += bv1;
        }
#pragma unroll
    for (int mt = 0; mt < 4; mt++) {
#pragma unroll
        for (int h = 0; h < 2; h++) {
            int row = wm * 64 + mt * 16 + g + h * 8;
            float mx = -1e30f;
#pragma unroll
            for (int nt = 0; nt < 4; nt++) {
                if (val[nt]) {
                    float e0 = acc[mt][nt][2 * h], e1 = acc[mt][nt][2 * h + 1];
                    *(float2*)&g_logits[(size_t)row * V_ + v0 + cbase + nt * 8] = make_float2(e0, e1);
                    mx = fmaxf(mx, fmaxf(e0, e1));
                }
            }
            mx = fmaxf(mx, __shfl_xor_sync(0xffffffffu, mx, 1));
            mx = fmaxf(mx, __shfl_xor_sync(0xffffffffu, mx, 2));
            if (tg == 0) s_red[row][wn] = mx;
        }
    }
    __syncthreads();
    if (tid < 128)
        s_rowmax[tid] = fmaxf(fmaxf(s_red[tid][0], s_red[tid][1]),
                              fmaxf(s_red[tid][2], s_red[tid][3]));
    __syncthreads();
#pragma unroll
    for (int mt = 0; mt < 4; mt++) {
#pragma unroll
        for (int h = 0; h < 2; h++) {
            int row = wm * 64 + mt * 16 + g + h * 8;
            float rm = s_rowmax[row], s = 0.0f;
#pragma unroll
            for (int nt = 0; nt < 4; nt++) {
                if (val[nt]) {
                    s += __expf(acc[mt][nt][2 * h] - rm);
                    s += __expf(acc[mt][nt][2 * h + 1] - rm);
                }
            }
            s += __shfl_xor_sync(0xffffffffu, s, 1);
            s += __shfl_xor_sync(0xffffffffu, s, 2);
            if (tg == 0) s_red[row][wn] = s;
        }
    }
    __syncthreads();
    if (tid < 128) {
        float s = s_red[tid][0] + s_red[tid][1] + s_red[tid][2] + s_red[tid][3];
        g_tmax[tid * NTILE + blockIdx.x] = s_rowmax[tid];
        g_tsum[tid * NTILE + blockIdx.x] = s;
    }
}

// =============== K11: combine tile partials ===============
__global__ void k_combine(const float* __restrict__ outp) {
    int b = blockIdx.x, tid = threadIdx.x;
    __shared__ float red[128];
    float m = -1e30f;
    for (int i = tid; i < NTILE; i += 128) m = fmaxf(m, g_tmax[b * NTILE + i]);
    red[tid] = m; __syncthreads();
    for (int s = 64; s > 0; s >>= 1) { if (tid < s) red[tid] = fmaxf(red[tid], red[tid + s]); __syncthreads(); }
    float M = red[0]; __syncthreads();
    float sum = 0.0f;
    for (int i = tid; i < NTILE; i += 128)
        sum += g_tsum[b * NTILE + i] * __expf(g_tmax[b * NTILE + i] - M);
    red[tid] = sum; __syncthreads();
    for (int s = 64; s > 0; s >>= 1) { if (tid < s) red[tid] += red[tid + s]; __syncthreads(); }
    if (tid == 0) {
        g_M[b] = M;
        g_scale[b] = __fdividef(outp[O_PG + b], red[0]);
    }
}

// =============== K12: final vocab dist ===============
__global__ void k_final_vocab(const float* __restrict__ extra_zeros, float* __restrict__ outp) {
    int v = blockIdx.x * 256 + threadIdx.x;
    int b = blockIdx.y;
    if (v < V_) {
        outp[O_FD + b * VX_ + v] = g_scale[b] * __expf(g_logits[b * V_ + v] - g_M[b]);
    } else if (v < VX_) {
        outp[O_FD + b * VX_ + v] = extra_zeros[b * X_ + (v - V_)];
    }
}

// =============== K13: pointer scatter-add ===============
__global__ void k_scatter(const int* __restrict__ ext_vocab, float* __restrict__ outp) {
    int i = blockIdx.x * 256 + threadIdx.x;
    int b = i >> 10;
    float pg = outp[O_PG + b];
    float av = outp[O_A + i];
    atomicAdd(&outp[O_FD + b * VX_ + ext_vocab[i]], (1.0f - pg) * av);
}

// ======================================================================
extern "C" void kernel_launch(void* const* d_in, const int* in_sizes, int n_in,
                              void* d_out, int out_size) {
    (void)in_sizes; (void)n_in; (void)out_size;
    const int*   y_t       = (const int*)d_in[0];
    const float* h0        = (const float*)d_in[1];
    const float* c0        = (const float*)d_in[2];
    const float* enc_outs  = (const float*)d_in[3];
    const float* enc_feats = (const float*)d_in[4];
    const float* mask      = (const float*)d_in[5];
    const float* c_t_1     = (const float*)d_in[6];
    const float* extra_z   = (const float*)d_in[7];
    const int*   ext_vocab = (const int*)d_in[8];
    const float* coverage  = (const float*)d_in[9];
    const float* embed_W   = (const float*)d_in[10];
    const float* Wih       = (const float*)d_in[11];
    const float* Whh       = (const float*)d_in[12];
    const float* bih       = (const float*)d_in[13];
    const float* bhh       = (const float*)d_in[14];
    const float* xctx_W    = (const float*)d_in[15];
    const float* xctx_b    = (const float*)d_in[16];
    const float* Ws_W      = (const float*)d_in[17];
    const float* Ws_b      = (const float*)d_in[18];
    const float* Wc_W      = (const float*)d_in[19];
    const float* v_W       = (const float*)d_in[20];
    const float* pgen_W    = (const float*)d_in[21];
    const float* pgen_b    = (const float*)d_in[22];
    const float* proj_W    = (const float*)d_in[23];
    const float* proj_b    = (const float*)d_in[24];
    const float* out_W     = (const float*)d_in[25];
    const float* out_b     = (const float*)d_in[26];
    float* outp = (float*)d_out;

    float* d_xT;     cudaGetSymbolAddress((void**)&d_xT, g_xT);
    float* d_gatesT; cudaGetSymbolAddress((void**)&d_gatesT, g_gatesT);
    float* d_hcT;    cudaGetSymbolAddress((void**)&d_hcT, g_hcT);
    float* d_decT;   cudaGetSymbolAddress((void**)&d_decT, g_decT);
    float* d_ctT;    cudaGetSymbolAddress((void**)&d_ctT, g_ctT);
    float* d_hidT;   cudaGetSymbolAddress((void**)&d_hidT, g_hidT);
    float* d_prepT;  cudaGetSymbolAddress((void**)&d_prepT, g_prepT);
    float* d_h0T;    cudaGetSymbolAddress((void**)&d_h0T, g_h0T);

    // side stream + events for fork-join capture (host handles only; no device mem;
    // created fresh per call -> identical captured work every call)
    cudaStream_t s2;
    cudaStreamCreateWithFlags(&s2, cudaStreamNonBlocking);
    cudaEvent_t ev0, evp, ev1, ev2;
    cudaEventCreateWithFlags(&ev0, cudaEventDisableTiming);
    cudaEventCreateWithFlags(&evp, cudaEventDisableTiming);
    cudaEventCreateWithFlags(&ev1, cudaEventDisableTiming);
    cudaEventCreateWithFlags(&ev2, cudaEventDisableTiming);

    // fork: prep on s2 overlaps zero on main
    cudaEventRecord(ev0, 0);
    cudaStreamWaitEvent(s2, ev0, 0);
    k_zero<<<512, 256>>>();
    k_prep<<<B_, 256, 0, s2>>>(y_t, c_t_1, embed_W, h0);
    cudaEventRecord(evp, s2);
    cudaStreamWaitEvent(0, evp, 0);

    // x = [c_t_1, emb] @ xctx_W.T + xctx_b   (K=640 -> 10 chunks)
    k_gemm<<<dim3(4, 4, 10), 256>>>(d_prepT, xctx_W, 640, 640,
                                    nullptr, nullptr, 0, xctx_b, nullptr, d_xT);
    // gates = x@Wih.T + h0@Whh.T + biases    (K=128+256 -> 6 chunks)
    k_gemm<<<dim3(32, 4, 6), 256>>>(d_xT, Wih, 128, 128,
                                    d_h0T, Whh, 256, bih, bhh, d_gatesT);
    k_lstm<<<128, 256>>>(c0, outp);

    // fork: h-half of hid GEMM overlaps the attention phase
    cudaEventRecord(ev1, 0);
    cudaStreamWaitEvent(s2, ev1, 0);
    k_gemm<<<dim3(8, 4, 4), 256, 0, s2>>>(d_hcT, proj_W, 768, 256,
                                          nullptr, nullptr, 0, proj_b, nullptr, d_hidT);
    cudaEventRecord(ev2, s2);

    // dec = [h,c]@Ws_W.T + Ws_b              (K=512 -> 8 chunks)
    k_gemm<<<dim3(16, 4, 8), 256>>>(d_hcT, Ws_W, 512, 512,
                                    nullptr, nullptr, 0, Ws_b, nullptr, d_decT);
    k_energy<<<B_ * L_ / 8, 256>>>(enc_feats, coverage, Wc_W, v_W);
    k_softmax_a<<<B_, 256>>>(mask, coverage, outp);
    k_ctx<<<dim3(16, B_), 256>>>(enc_outs, outp);
    k_finalize<<<B_, 512>>>(pgen_W, pgen_b, outp);

    // ct-half of hid GEMM (K=512 -> 8 chunks), no bias (added in h-half)
    k_gemm<<<dim3(8, 4, 8), 256>>>(d_ctT, proj_W + 256, 768, 512,
                                   nullptr, nullptr, 0, nullptr, nullptr, d_hidT);
    // join: logits needs both hid halves
    cudaStreamWaitEvent(0, ev2, 0);
    k_logits_mma<<<NTILE, 256>>>(out_W, out_b);
    k_combine<<<B_, 128>>>(outp);
    k_final_vocab<<<dim3(196, B_), 256>>>(extra_z, outp);
    k_scatter<<<B_ * L_ / 256, 256>>>(ext_vocab, outp);
}

// round 6
// speedup vs baseline: 2.0979x; 1.1296x over previous
#include <cuda_runtime.h>
#include <cuda_bf16.h>
#include <cstdint>

#define B_ 128
#define L_ 1024
#define H_ 256
#define E_ 128
#define V_ 50000
#define X_ 100
#define VX_ 50100
#define NTILE 391

// d_out float offsets (tuple order: final_dist, h, c, c_t, a, p_gen, coverage_next)
#define O_FD  0
#define O_H   6412800
#define O_C   6445568
#define O_CT  6478336
#define O_A   6543872
#define O_PG  6674944
#define O_COV 6675072

// ---------------- static device scratch (no allocations) ----------------
__device__ __align__(256) float g_prepT[640 * B_];
__device__ __align__(256) float g_h0T[256 * B_];
__device__ __align__(256) float g_xT[E_ * B_];
__device__ __align__(256) float g_gatesT[4 * H_ * B_];
__device__ __align__(256) float g_hcT[2 * H_ * B_];
__device__ __align__(256) float g_decT[2 * H_ * B_];
__device__ __align__(256) float g_ctT[2 * H_ * B_];
__device__ __align__(256) float g_hidT[H_ * B_];          // [k][b]
__device__ __align__(256) float g_energy[B_ * L_];
__device__ __align__(256) float g_ctp[B_ * 16 * 2 * H_];
__device__ __align__(256) float g_logits[B_ * V_];
__device__ __align__(256) float g_tmax[B_ * NTILE];
__device__ __align__(256) float g_tsum[B_ * NTILE];
__device__ __align__(256) float g_M[B_];
__device__ __align__(256) float g_scale[B_];

// ---------------- helpers ----------------
__device__ __forceinline__ float fsig(float x) {
    return __fdividef(1.0f, 1.0f + __expf(-x));
}
__device__ __forceinline__ float ftanh(float x) {
    float e = __expf(2.0f * x);
    return 1.0f - __fdividef(2.0f, 1.0f + e);
}
__device__ __forceinline__ uint32_t pkbf2(float a, float b) {
    uint32_t r;
    asm("cvt.rn.bf16x2.f32 %0, %2, %1;" : "=r"(r) : "f"(a), "f"(b));
    return r;
}

// =============== K0: zero scratch + prep transposed activations (fused) ===============
__global__ void k_prep_zero(const int* __restrict__ y_t, const float* __restrict__ c_t_1,
                            const float* __restrict__ embed_W, const float* __restrict__ h0) {
    int bid = blockIdx.x, t = threadIdx.x;     // grid 512 x 256
    int i = bid * 256 + t;
    if (i < E_ * B_)      g_xT[i] = 0.0f;
    if (i < 4 * H_ * B_)  g_gatesT[i] = 0.0f;
    if (i < 2 * H_ * B_)  g_decT[i] = 0.0f;
    if (i < H_ * B_)      g_hidT[i] = 0.0f;
    if (bid < B_) {
        int b = bid;
        for (int k = t; k < 512; k += 256) g_prepT[k * 128 + b] = c_t_1[b * 512 + k];
        int y = y_t[b];
        if (t < 128) g_prepT[(512 + t) * 128 + b] = embed_W[y * 128 + t];
        g_h0T[t * 128 + b] = h0[b * 256 + t];
    }
}

// =============== unified small GEMM (1 chunk of 64 k per block) ===============
__global__ void __launch_bounds__(256) k_gemm(
    const float* __restrict__ actA, const float* __restrict__ WA, int sWA, int KA,
    const float* __restrict__ actB, const float* __restrict__ WB, int sWB,
    const float* __restrict__ bias1, const float* __restrict__ bias2,
    float* __restrict__ outT)
{
    __shared__ float s_act[32][65];
    __shared__ float s_w[32][64];
    int tid = threadIdx.x;
    int lane = tid & 31, wp = tid >> 5;
    int j0 = blockIdx.x * 32;
    int b  = blockIdx.y * 32 + lane;
    int k0 = blockIdx.z * 64;

    const float* asrc; const float* wsrc; int ws; int kr;
    if (k0 < KA) { asrc = actA; wsrc = WA; ws = sWA; kr = k0; }
    else         { asrc = actB; wsrc = WB; ws = sWB; kr = k0 - KA; }
#pragma unroll
    for (int r = 0; r < 8; r++) {
        int k = r * 8 + wp;
        s_act[lane][k] = asrc[(kr + k) * 128 + b];
    }
    {
        int idx = tid * 2;
        int j = idx >> 4, f = (idx & 15) * 4;
        float4 v = *(const float4*)&wsrc[(j0 + j) * ws + kr + f];
        *(float4*)&s_w[j][f] = v;
        idx++;
        j = idx >> 4; f = (idx & 15) * 4;
        v = *(const float4*)&wsrc[(j0 + j) * ws + kr + f];
        *(float4*)&s_w[j][f] = v;
    }
    __syncthreads();
    float acc0 = 0.0f, acc1 = 0.0f, acc2 = 0.0f, acc3 = 0.0f;
#pragma unroll
    for (int kk = 0; kk < 64; kk += 4) {
        float a0 = s_act[lane][kk + 0];
        float a1 = s_act[lane][kk + 1];
        float a2 = s_act[lane][kk + 2];
        float a3 = s_act[lane][kk + 3];
        float4 w0 = *(const float4*)&s_w[wp * 4 + 0][kk];
        float4 w1 = *(const float4*)&s_w[wp * 4 + 1][kk];
        float4 w2 = *(const float4*)&s_w[wp * 4 + 2][kk];
        float4 w3 = *(const float4*)&s_w[wp * 4 + 3][kk];
        acc0 += w0.x * a0 + w0.y * a1 + w0.z * a2 + w0.w * a3;
        acc1 += w1.x * a0 + w1.y * a1 + w1.z * a2 + w1.w * a3;
        acc2 += w2.x * a0 + w2.y * a1 + w2.z * a2 + w2.w * a3;
        acc3 += w3.x * a0 + w3.y * a1 + w3.z * a2 + w3.w * a3;
    }
    int j = j0 + wp * 4;
    if (blockIdx.z == 0 && bias1) {
        acc0 += bias1[j + 0]; acc1 += bias1[j + 1]; acc2 += bias1[j + 2]; acc3 += bias1[j + 3];
        if (bias2) {
            acc0 += bias2[j + 0]; acc1 += bias2[j + 1]; acc2 += bias2[j + 2]; acc3 += bias2[j + 3];
        }
    }
    atomicAdd(&outT[(j + 0) * 128 + b], acc0);
    atomicAdd(&outT[(j + 1) * 128 + b], acc1);
    atomicAdd(&outT[(j + 2) * 128 + b], acc2);
    atomicAdd(&outT[(j + 3) * 128 + b], acc3);
}

// =============== K3: LSTM pointwise ===============
__global__ void k_lstm(const float* __restrict__ c0, float* __restrict__ outp) {
    int i = blockIdx.x * 256 + threadIdx.x;
    int t = i >> 7, b = i & 127;
    float gi = g_gatesT[i];
    float gf = g_gatesT[i + 32768];
    float gg = g_gatesT[i + 65536];
    float go = g_gatesT[i + 98304];
    float c0v = c0[b * 256 + t];
    float cc = fsig(gf) * c0v + fsig(gi) * ftanh(gg);
    float hh = fsig(go) * ftanh(cc);
    outp[O_H + b * 256 + t] = hh;
    outp[O_C + b * 256 + t] = cc;
    g_hcT[t * 128 + b] = hh;
    g_hcT[(256 + t) * 128 + b] = cc;
}

// =============== K5: attention energy (streams enc_feats) ===============
__global__ void k_energy(const float* __restrict__ enc_feats,
                         const float* __restrict__ coverage,
                         const float* __restrict__ Wc_W, const float* __restrict__ v_W) {
    int idx0 = blockIdx.x * 8;
    int b = idx0 >> 10;
    __shared__ float sdec[512], swc[512], sv[512];
    int tid = threadIdx.x;
    for (int i = tid; i < 512; i += 256) {
        sdec[i] = g_decT[i * 128 + b];
        swc[i]  = Wc_W[i];
        sv[i]   = v_W[i];
    }
    __syncthreads();
    int w = tid >> 5, lane = tid & 31;
    int idx = idx0 + w;
    float cov = coverage[idx];
    const float* base = enc_feats + (size_t)idx * 512;
    float e = 0.0f;
#pragma unroll
    for (int c = 0; c < 4; c++) {
        int d0 = c * 128 + lane * 4;
        float4 f  = *(const float4*)(base + d0);
        float4 dv = *(const float4*)(sdec + d0);
        float4 wv = *(const float4*)(swc + d0);
        float4 vv = *(const float4*)(sv + d0);
        e += ftanh(f.x + dv.x + cov * wv.x) * vv.x;
        e += ftanh(f.y + dv.y + cov * wv.y) * vv.y;
        e += ftanh(f.z + dv.z + cov * wv.z) * vv.z;
        e += ftanh(f.w + dv.w + cov * wv.w) * vv.w;
    }
#pragma unroll
    for (int o = 16; o; o >>= 1) e += __shfl_xor_sync(0xffffffffu, e, o);
    if (lane == 0) g_energy[idx] = e;
}

// =============== K6: softmax over L ===============
__global__ void k_softmax_a(const float* __restrict__ mask, const float* __restrict__ coverage,
                            float* __restrict__ outp) {
    int b = blockIdx.x, tid = threadIdx.x;
    __shared__ float red[256];
    float e[4];
#pragma unroll
    for (int j = 0; j < 4; j++) e[j] = g_energy[b * 1024 + tid + j * 256];
    float m = fmaxf(fmaxf(e[0], e[1]), fmaxf(e[2], e[3]));
    red[tid] = m; __syncthreads();
    for (int s = 128; s > 0; s >>= 1) { if (tid < s) red[tid] = fmaxf(red[tid], red[tid + s]); __syncthreads(); }
    float M = red[0]; __syncthreads();
    float ev[4], sum = 0.0f;
#pragma unroll
    for (int j = 0; j < 4; j++) {
        ev[j] = __expf(e[j] - M) * mask[b * 1024 + tid + j * 256];
        sum += ev[j];
    }
    red[tid] = sum; __syncthreads();
    for (int s = 128; s > 0; s >>= 1) { if (tid < s) red[tid] += red[tid + s]; __syncthreads(); }
    float inv = __fdividef(1.0f, red[0]);
#pragma unroll
    for (int j = 0; j < 4; j++) {
        int i = b * 1024 + tid + j * 256;
        float a = ev[j] * inv;
        outp[O_A + i] = a;
        outp[O_COV + i] = coverage[i] + a;
    }
}

// =============== K7: c_t partials (streams enc_outs) ===============
__global__ void k_ctx(const float* __restrict__ enc_outs, const float* __restrict__ outp) {
    int chunk = blockIdx.x, b = blockIdx.y;
    __shared__ float sa[64];
    int tid = threadIdx.x;
    if (tid < 64) sa[tid] = outp[O_A + b * 1024 + chunk * 64 + tid];
    __syncthreads();
    const float2* p = (const float2*)(enc_outs + ((size_t)b * 1024 + chunk * 64) * 512);
    float2 acc = make_float2(0.0f, 0.0f);
#pragma unroll 8
    for (int i = 0; i < 64; i++) {
        float2 v = p[i * 256 + tid];
        float a = sa[i];
        acc.x += a * v.x;
        acc.y += a * v.y;
    }
    *(float2*)&g_ctp[(b * 16 + chunk) * 512 + 2 * tid] = acc;
}

// =============== K8: reduce c_t, p_gen ===============
__global__ void k_finalize(const float* __restrict__ pgen_W, const float* __restrict__ pgen_b,
                           float* __restrict__ outp) {
    int b = blockIdx.x, tid = threadIdx.x;
    __shared__ float sct[512];
    __shared__ float red[512];
    float s = 0.0f;
#pragma unroll
    for (int ch = 0; ch < 16; ch++) s += g_ctp[(b * 16 + ch) * 512 + tid];
    sct[tid] = s;
    outp[O_CT + b * 512 + tid] = s;
    g_ctT[tid * 128 + b] = s;
    __syncthreads();
    float p = pgen_W[tid] * sct[tid];
    float z2 = (tid < 256) ? outp[O_H + b * 256 + tid] : outp[O_C + b * 256 + (tid - 256)];
    p += pgen_W[512 + tid] * z2;
    if (tid < 128) p += pgen_W[1024 + tid] * g_xT[tid * 128 + b];
    red[tid] = p; __syncthreads();
    for (int st = 256; st > 0; st >>= 1) { if (tid < st) red[tid] += red[tid + st]; __syncthreads(); }
    if (tid == 0) outp[O_PG + b] = fsig(red[0] + pgen_b[0]);
}

// =============== K10: pipelined logits GEMM on tensor cores ===============
// A (hid) staged ONCE to smem bf16 (stride 132 words: conflict-free frags).
// B double-buffered (stride 20 words), register-prefetch of next tile before compute.
#define SA_STRIDE 132
#define SB_STRIDE 20
#define SB_WORDS  (128 * SB_STRIDE)
#define SMEM_LOGITS ((128 * SA_STRIDE + 2 * SB_WORDS) * 4 + 128 * 4 + 128 * 4 * 4 + 128 * 4)

__global__ void __launch_bounds__(256) k_logits_mma(const float* __restrict__ outW,
                                                    const float* __restrict__ outb) {
    const int v0 = blockIdx.x * 128;
    extern __shared__ uint32_t smem_dyn[];
    uint32_t* sA = smem_dyn;                            // 128*132 words
    uint32_t* sB = sA + 128 * SA_STRIDE;                // 2 * SB_WORDS
    float* s_bias   = (float*)(sB + 2 * SB_WORDS);      // 128
    float* s_red    = s_bias + 128;                     // [128][4]
    float* s_rowmax = s_red + 512;                      // 128

    int tid = threadIdx.x;
    int lane = tid & 31, wid = tid >> 5;
    int wm = wid >> 2, wn = wid & 3;
    int g = lane >> 2, tg = lane & 3;

    if (tid < 128) {
        int v = v0 + tid;
        s_bias[tid] = (v < V_) ? outb[v] : 0.0f;
    }

    // --- prologue: issue B0 loads first (DRAM), then stage A (L2) under their latency ---
    float4 pw[4];
#pragma unroll
    for (int r = 0; r < 4; r++) {
        int idx = r * 256 + tid;
        int v = idx >> 3, f = idx & 7;
        pw[r] = (v0 + v < V_) ? *(const float4*)&outW[(size_t)(v0 + v) * 256 + f * 4]
                              : make_float4(0.f, 0.f, 0.f, 0.f);
    }
#pragma unroll 8
    for (int r = 0; r < 64; r++) {
        int idx = r * 256 + tid;
        int b = idx & 127, w = idx >> 7;                // w in 0..127
        float lo = g_hidT[(2 * w) * 128 + b];
        float hi = g_hidT[(2 * w + 1) * 128 + b];
        sA[b * SA_STRIDE + w] = pkbf2(lo, hi);
    }
#pragma unroll
    for (int r = 0; r < 4; r++) {
        int idx = r * 256 + tid;
        int v = idx >> 3, f = idx & 7;
        sB[v * SB_STRIDE + f * 2]     = pkbf2(pw[r].x, pw[r].y);
        sB[v * SB_STRIDE + f * 2 + 1] = pkbf2(pw[r].z, pw[r].w);
    }
    __syncthreads();

    float acc[4][4][4];
#pragma unroll
    for (int mt = 0; mt < 4; mt++)
#pragma unroll
        for (int nt = 0; nt < 4; nt++)
#pragma unroll
            for (int q = 0; q < 4; q++) acc[mt][nt][q] = 0.0f;

#pragma unroll 1
    for (int it = 0; it < 8; it++) {
        // prefetch next B tile into registers (overlaps with compute below)
        if (it < 7) {
            int k0n = (it + 1) * 32;
#pragma unroll
            for (int r = 0; r < 4; r++) {
                int idx = r * 256 + tid;
                int v = idx >> 3, f = idx & 7;
                pw[r] = (v0 + v < V_) ? *(const float4*)&outW[(size_t)(v0 + v) * 256 + k0n + f * 4]
                                      : make_float4(0.f, 0.f, 0.f, 0.f);
            }
        }
        // compute on current buffer
        const uint32_t* sBp = sB + (it & 1) * SB_WORDS;
        int aw = it * 16;
#pragma unroll
        for (int kk = 0; kk < 2; kk++) {
            int kw = kk * 8 + tg;
            uint32_t a[4][4];
#pragma unroll
            for (int mt = 0; mt < 4; mt++) {
                int r0 = wm * 64 + mt * 16 + g;
                a[mt][0] = sA[r0 * SA_STRIDE + aw + kw];
                a[mt][1] = sA[(r0 + 8) * SA_STRIDE + aw + kw];
                a[mt][2] = sA[r0 * SA_STRIDE + aw + kw + 4];
                a[mt][3] = sA[(r0 + 8) * SA_STRIDE + aw + kw + 4];
            }
#pragma unroll
            for (int nt = 0; nt < 4; nt++) {
                int n0 = wn * 32 + nt * 8 + g;
                uint32_t b0 = sBp[n0 * SB_STRIDE + kw];
                uint32_t b1 = sBp[n0 * SB_STRIDE + kw + 4];
#pragma unroll
                for (int mt = 0; mt < 4; mt++) {
                    asm volatile(
                        "mma.sync.aligned.m16n8k16.row.col.f32.bf16.bf16.f32 "
                        "{%0,%1,%2,%3},{%4,%5,%6,%7},{%8,%9},{%0,%1,%2,%3};"
                        : "+f"(acc[mt][nt][0]), "+f"(acc[mt][nt][1]),
                          "+f"(acc[mt][nt][2]), "+f"(acc[mt][nt][3])
                        : "r"(a[mt][0]), "r"(a[mt][1]), "r"(a[mt][2]), "r"(a[mt][3]),
                          "r"(b0), "r"(b1));
                }
            }
        }
        // store prefetched tile into the other buffer (safe: all warps past iter it-1)
        if (it < 7) {
            uint32_t* sBn = sB + ((it + 1) & 1) * SB_WORDS;
#pragma unroll
            for (int r = 0; r < 4; r++) {
                int idx = r * 256 + tid;
                int v = idx >> 3, f = idx & 7;
                sBn[v * SB_STRIDE + f * 2]     = pkbf2(pw[r].x, pw[r].y);
                sBn[v * SB_STRIDE + f * 2 + 1] = pkbf2(pw[r].z, pw[r].w);
            }
        }
        __syncthreads();
    }

    // ---- epilogue: bias, store logits, per-row max/sumexp over this 128-col tile ----
    int cbase = wn * 32 + tg * 2;
    bool val[4];
#pragma unroll
    for (int nt = 0; nt < 4; nt++) val[nt] = (v0 + cbase + nt * 8) < V_;
#pragma unroll
    for (int mt = 0; mt < 4; mt++)
#pragma unroll
        for (int nt = 0; nt < 4; nt++) {
            float bv0 = s_bias[cbase + nt * 8];
            float bv1 = s_bias[cbase + nt * 8 + 1];
            acc[mt][nt][0] += bv0; acc[mt][nt][1] += bv1;
            acc[mt][nt][2] += bv0; acc[mt][nt][3] += bv1;
        }
#pragma unroll
    for (int mt = 0; mt < 4; mt++) {
#pragma unroll
        for (int h = 0; h < 2; h++) {
            int row = wm * 64 + mt * 16 + g + h * 8;
            float mx = -1e30f;
#pragma unroll
            for (int nt = 0; nt < 4; nt++) {
                if (val[nt]) {
                    float e0 = acc[mt][nt][2 * h], e1 = acc[mt][nt][2 * h + 1];
                    *(float2*)&g_logits[(size_t)row * V_ + v0 + cbase + nt * 8] = make_float2(e0, e1);
                    mx = fmaxf(mx, fmaxf(e0, e1));
                }
            }
            mx = fmaxf(mx, __shfl_xor_sync(0xffffffffu, mx, 1));
            mx = fmaxf(mx, __shfl_xor_sync(0xffffffffu, mx, 2));
            if (tg == 0) s_red[row * 4 + wn] = mx;
        }
    }
    __syncthreads();
    if (tid < 128)
        s_rowmax[tid] = fmaxf(fmaxf(s_red[tid * 4 + 0], s_red[tid * 4 + 1]),
                              fmaxf(s_red[tid * 4 + 2], s_red[tid * 4 + 3]));
    __syncthreads();
#pragma unroll
    for (int mt = 0; mt < 4; mt++) {
#pragma unroll
        for (int h = 0; h < 2; h++) {
            int row = wm * 64 + mt * 16 + g + h * 8;
            float rm = s_rowmax[row], s = 0.0f;
#pragma unroll
            for (int nt = 0; nt < 4; nt++) {
                if (val[nt]) {
                    s += __expf(acc[mt][nt][2 * h] - rm);
                    s += __expf(acc[mt][nt][2 * h + 1] - rm);
                }
            }
            s += __shfl_xor_sync(0xffffffffu, s, 1);
            s += __shfl_xor_sync(0xffffffffu, s, 2);
            if (tg == 0) s_red[row * 4 + wn] = s;
        }
    }
    __syncthreads();
    if (tid < 128) {
        float s = s_red[tid * 4 + 0] + s_red[tid * 4 + 1] + s_red[tid * 4 + 2] + s_red[tid * 4 + 3];
        g_tmax[tid * NTILE + blockIdx.x] = s_rowmax[tid];
        g_tsum[tid * NTILE + blockIdx.x] = s;
    }
}

// =============== K11: combine tile partials ===============
__global__ void k_combine(const float* __restrict__ outp) {
    int b = blockIdx.x, tid = threadIdx.x;
    __shared__ float red[128];
    float m = -1e30f;
    for (int i = tid; i < NTILE; i += 128) m = fmaxf(m, g_tmax[b * NTILE + i]);
    red[tid] = m; __syncthreads();
    for (int s = 64; s > 0; s >>= 1) { if (tid < s) red[tid] = fmaxf(red[tid], red[tid + s]); __syncthreads(); }
    float M = red[0]; __syncthreads();
    float sum = 0.0f;
    for (int i = tid; i < NTILE; i += 128)
        sum += g_tsum[b * NTILE + i] * __expf(g_tmax[b * NTILE + i] - M);
    red[tid] = sum; __syncthreads();
    for (int s = 64; s > 0; s >>= 1) { if (tid < s) red[tid] += red[tid + s]; __syncthreads(); }
    if (tid == 0) {
        g_M[b] = M;
        g_scale[b] = __fdividef(outp[O_PG + b], red[0]);
    }
}

// =============== K12: final vocab dist (float4) ===============
__global__ void k_final_vocab(const float* __restrict__ extra_zeros, float* __restrict__ outp) {
    int q = blockIdx.x * 256 + threadIdx.x;      // float4 index within row
    int b = blockIdx.y;
    if (q < 12500) {                             // covers v 0..49999 exactly
        float4 lg = *(const float4*)&g_logits[(size_t)b * V_ + q * 4];
        float M = g_M[b], sc = g_scale[b];
        float4 o;
        o.x = sc * __expf(lg.x - M);
        o.y = sc * __expf(lg.y - M);
        o.z = sc * __expf(lg.z - M);
        o.w = sc * __expf(lg.w - M);
        *(float4*)&outp[O_FD + (size_t)b * VX_ + q * 4] = o;
    } else if (q < 12525) {                      // extra zeros v 50000..50099
        int v = q * 4 - V_;
        float4 z = *(const float4*)&extra_zeros[b * X_ + v];
        *(float4*)&outp[O_FD + (size_t)b * VX_ + q * 4] = z;
    }
}

// =============== K13: pointer scatter-add ===============
__global__ void k_scatter(const int* __restrict__ ext_vocab, float* __restrict__ outp) {
    int i = blockIdx.x * 256 + threadIdx.x;
    int b = i >> 10;
    float pg = outp[O_PG + b];
    float av = outp[O_A + i];
    atomicAdd(&outp[O_FD + b * VX_ + ext_vocab[i]], (1.0f - pg) * av);
}

// ======================================================================
extern "C" void kernel_launch(void* const* d_in, const int* in_sizes, int n_in,
                              void* d_out, int out_size) {
    (void)in_sizes; (void)n_in; (void)out_size;
    const int*   y_t       = (const int*)d_in[0];
    const float* h0        = (const float*)d_in[1];
    const float* c0        = (const float*)d_in[2];
    const float* enc_outs  = (const float*)d_in[3];
    const float* enc_feats = (const float*)d_in[4];
    const float* mask      = (const float*)d_in[5];
    const float* c_t_1     = (const float*)d_in[6];
    const float* extra_z   = (const float*)d_in[7];
    const int*   ext_vocab = (const int*)d_in[8];
    const float* coverage  = (const float*)d_in[9];
    const float* embed_W   = (const float*)d_in[10];
    const float* Wih       = (const float*)d_in[11];
    const float* Whh       = (const float*)d_in[12];
    const float* bih       = (const float*)d_in[13];
    const float* bhh       = (const float*)d_in[14];
    const float* xctx_W    = (const float*)d_in[15];
    const float* xctx_b    = (const float*)d_in[16];
    const float* Ws_W      = (const float*)d_in[17];
    const float* Ws_b      = (const float*)d_in[18];
    const float* Wc_W      = (const float*)d_in[19];
    const float* v_W       = (const float*)d_in[20];
    const float* pgen_W    = (const float*)d_in[21];
    const float* pgen_b    = (const float*)d_in[22];
    const float* proj_W    = (const float*)d_in[23];
    const float* proj_b    = (const float*)d_in[24];
    const float* out_W     = (const float*)d_in[25];
    const float* out_b     = (const float*)d_in[26];
    float* outp = (float*)d_out;

    float* d_xT;     cudaGetSymbolAddress((void**)&d_xT, g_xT);
    float* d_gatesT; cudaGetSymbolAddress((void**)&d_gatesT, g_gatesT);
    float* d_hcT;    cudaGetSymbolAddress((void**)&d_hcT, g_hcT);
    float* d_decT;   cudaGetSymbolAddress((void**)&d_decT, g_decT);
    float* d_ctT;    cudaGetSymbolAddress((void**)&d_ctT, g_ctT);
    float* d_hidT;   cudaGetSymbolAddress((void**)&d_hidT, g_hidT);
    float* d_prepT;  cudaGetSymbolAddress((void**)&d_prepT, g_prepT);
    float* d_h0T;    cudaGetSymbolAddress((void**)&d_h0T, g_h0T);

    cudaFuncSetAttribute(k_logits_mma, cudaFuncAttributeMaxDynamicSharedMemorySize, SMEM_LOGITS);

    // side stream + events for fork-join capture (host handles only; no device mem)
    cudaStream_t s2;
    cudaStreamCreateWithFlags(&s2, cudaStreamNonBlocking);
    cudaEvent_t ev1, ev2;
    cudaEventCreateWithFlags(&ev1, cudaEventDisableTiming);
    cudaEventCreateWithFlags(&ev2, cudaEventDisableTiming);

    k_prep_zero<<<512, 256>>>(y_t, c_t_1, embed_W, h0);

    // x = [c_t_1, emb] @ xctx_W.T + xctx_b   (K=640 -> 10 chunks)
    k_gemm<<<dim3(4, 4, 10), 256>>>(d_prepT, xctx_W, 640, 640,
                                    nullptr, nullptr, 0, xctx_b, nullptr, d_xT);
    // gates = x@Wih.T + h0@Whh.T + biases    (K=128+256 -> 6 chunks)
    k_gemm<<<dim3(32, 4, 6), 256>>>(d_xT, Wih, 128, 128,
                                    d_h0T, Whh, 256, bih, bhh, d_gatesT);
    k_lstm<<<128, 256>>>(c0, outp);

    // fork: h-half of hid GEMM overlaps the attention phase
    cudaEventRecord(ev1, 0);
    cudaStreamWaitEvent(s2, ev1, 0);
    k_gemm<<<dim3(8, 4, 4), 256, 0, s2>>>(d_hcT, proj_W, 768, 256,
                                          nullptr, nullptr, 0, proj_b, nullptr, d_hidT);
    cudaEventRecord(ev2, s2);

    // dec = [h,c]@Ws_W.T + Ws_b              (K=512 -> 8 chunks)
    k_gemm<<<dim3(16, 4, 8), 256>>>(d_hcT, Ws_W, 512, 512,
                                    nullptr, nullptr, 0, Ws_b, nullptr, d_decT);
    k_energy<<<B_ * L_ / 8, 256>>>(enc_feats, coverage, Wc_W, v_W);
    k_softmax_a<<<B_, 256>>>(mask, coverage, outp);
    k_ctx<<<dim3(16, B_), 256>>>(enc_outs, outp);
    k_finalize<<<B_, 512>>>(pgen_W, pgen_b, outp);

    // ct-half of hid GEMM (K=512 -> 8 chunks), no bias (added in h-half)
    k_gemm<<<dim3(8, 4, 8), 256>>>(d_ctT, proj_W + 256, 768, 512,
                                   nullptr, nullptr, 0, nullptr, nullptr, d_hidT);
    // join: logits needs both hid halves
    cudaStreamWaitEvent(0, ev2, 0);
    k_logits_mma<<<NTILE, 256, SMEM_LOGITS>>>(out_W, out_b);
    k_combine<<<B_, 128>>>(outp);
    k_final_vocab<<<dim3(49, B_), 256>>>(extra_z, outp);
    k_scatter<<<B_ * L_ / 256, 256>>>(ext_vocab, outp);
}